// round 1
// baseline (speedup 1.0000x reference)
#include <cuda_runtime.h>
#include <cuda_bf16.h>
#include <cstdint>

// Problem constants (fixed shapes)
#define BB 4096
#define DD 4096
#define HH 4096
#define OO 1000
#define PP 2048

// ---------------- scratch (device globals; no allocation) ----------------
__device__ float g_h   [(size_t)BB * HH];   // h / mean_reg / h1 (reused)
__device__ float g_hr  [(size_t)BB * HH];
__device__ float g_xrec[(size_t)BB * DD];
__device__ float g_lreg[(size_t)BB * DD];
__device__ float g_comb[(size_t)BB * DD];
__device__ float g_var [(size_t)BB * PP];
__device__ float g_w   [(size_t)BB * PP];

__device__ int g_na;
__device__ int g_perm[BB];
__device__ int g_newpos[BB];
__device__ int g_act[BB];
__device__ int g_posinact[BB];
__device__ int g_mask[BB];

// ---------------- helpers ----------------
__device__ __forceinline__ unsigned long long pack2(float x, float y) {
    unsigned long long r;
    asm("mov.b64 %0, {%1, %2};" : "=l"(r) : "f"(x), "f"(y));
    return r;
}
__device__ __forceinline__ float2 unpack2(unsigned long long v) {
    float2 r;
    asm("mov.b64 {%0, %1}, %2;" : "=f"(r.x), "=f"(r.y) : "l"(v));
    return r;
}
__device__ __forceinline__ void fma2(unsigned long long& c, unsigned long long a,
                                     unsigned long long b) {
    asm("fma.rn.f32x2 %0, %1, %2, %0;" : "+l"(c) : "l"(a), "l"(b));
}
__device__ __forceinline__ float softplusf(float z) {
    // logaddexp(z, 0) = max(z,0) + log1p(exp(-|z|))
    return fmaxf(z, 0.0f) + log1pf(expf(-fabsf(z)));
}

// ---------------- setup: mask, stable-partition perm, active set ----------------
__global__ void setup_kernel(const int* __restrict__ mm) {
    __shared__ int wsum[32];
    __shared__ int sTot[2];
    int tid = threadIdx.x, lane = tid & 31, warp = tid >> 5;
    int base = tid * 4;

    // ---- scan 1: ones (mask) ----
    int f[4], incl[4];
    int s = 0;
#pragma unroll
    for (int j = 0; j < 4; ++j) {
        f[j] = (mm[base + j] % 2 != 0) ? 1 : 0;
        s += f[j];
        incl[j] = s;
    }
    int v = s;
#pragma unroll
    for (int o = 1; o < 32; o <<= 1) {
        int u = __shfl_up_sync(0xffffffffu, v, o);
        if (lane >= o) v += u;
    }
    if (lane == 31) wsum[warp] = v;
    __syncthreads();
    if (warp == 0) {
        int w = wsum[lane];
#pragma unroll
        for (int o = 1; o < 32; o <<= 1) {
            int u = __shfl_up_sync(0xffffffffu, w, o);
            if (lane >= o) w += u;
        }
        wsum[lane] = w;
        if (lane == 31) sTot[0] = w;
    }
    __syncthreads();
    int T = sTot[0];
    int Z = BB - T;
    int thrExcl = (warp ? wsum[warp - 1] : 0) + (v - s);

    int af[4];
#pragma unroll
    for (int j = 0; j < 4; ++j) {
        int i = base + j;
        int onesBefore = thrExcl + incl[j] - f[j];
        int pos = f[j] ? (Z + onesBefore) : (i - onesBefore);
        g_mask[i] = f[j];
        g_newpos[i] = pos;
        g_perm[pos] = i;
        af[j] = (f[j] || pos >= BB / 2) ? 1 : 0;
    }
    __syncthreads();

    // ---- scan 2: active rows (need VAE path) ----
    int incl2[4];
    int s2 = 0;
#pragma unroll
    for (int j = 0; j < 4; ++j) { s2 += af[j]; incl2[j] = s2; }
    int v2 = s2;
#pragma unroll
    for (int o = 1; o < 32; o <<= 1) {
        int u = __shfl_up_sync(0xffffffffu, v2, o);
        if (lane >= o) v2 += u;
    }
    if (lane == 31) wsum[warp] = v2;
    __syncthreads();
    if (warp == 0) {
        int w = wsum[lane];
#pragma unroll
        for (int o = 1; o < 32; o <<= 1) {
            int u = __shfl_up_sync(0xffffffffu, w, o);
            if (lane >= o) w += u;
        }
        wsum[lane] = w;
        if (lane == 31) sTot[1] = w;
    }
    __syncthreads();
    int thrExcl2 = (warp ? wsum[warp - 1] : 0) + (v2 - s2);
#pragma unroll
    for (int j = 0; j < 4; ++j) {
        int i = base + j;
        int actBefore = thrExcl2 + incl2[j] - af[j];
        if (af[j]) {
            g_act[actBefore] = i;
            g_posinact[i] = actBefore;
        } else {
            g_posinact[i] = -1;
        }
    }
    if (tid == 0) g_na = sTot[1];
}

// ---------------- GEMM: C[M,N] = op(A[M,K]) * B + bias, fused epilogues ----------------
// flags: bit0 = M comes from g_na (early-exit grid)
//        bit1 = gather A rows via g_act
//        bit2 = B is K-major [K,N] ("NN"); else B is [N,K] row-major ("NT", C = A*B^T)
//        bits4+ = epilogue: 0 = +bias, 1 = relu(+bias), 2 = var/w (exp, sqrt, eps_w)
#define BM 128
#define BN 128
#define BK 16

__global__ void __launch_bounds__(256, 2)
gemm_kernel(const float* __restrict__ A, const float* __restrict__ Bm,
            const float* __restrict__ bias, float* __restrict__ C,
            float* __restrict__ C2, const float* __restrict__ eps,
            int M, int N, int K, int flags) {
    int Meff = (flags & 1) ? g_na : M;
    int mTile = blockIdx.y * BM;
    if (mTile >= Meff) return;
    int nTile = blockIdx.x * BN;

    __shared__ float As[BK][BM];
    __shared__ float Bs[BK][BN];

    int tid = threadIdx.x;
    int tx = tid & 15, ty = tid >> 4;
    const bool gather = (flags & 2) != 0;
    const bool bnn = (flags & 4) != 0;

    int arow = tid >> 2;          // 0..63
    int acol = (tid & 3) * 4;     // 0,4,8,12

    unsigned long long acc[8][4] = {};

    for (int k0 = 0; k0 < K; k0 += BK) {
        // load A tile (transposed into As[k][m])
#pragma unroll
        for (int rr = 0; rr < 2; ++rr) {
            int ml = arow + rr * 64;
            int m = mTile + ml;
            float4 vv = make_float4(0.f, 0.f, 0.f, 0.f);
            if (m < Meff) {
                int row = gather ? g_act[m] : m;
                vv = *reinterpret_cast<const float4*>(A + (size_t)row * K + k0 + acol);
            }
            As[acol + 0][ml] = vv.x;
            As[acol + 1][ml] = vv.y;
            As[acol + 2][ml] = vv.z;
            As[acol + 3][ml] = vv.w;
        }
        // load B tile
        if (!bnn) {
#pragma unroll
            for (int rr = 0; rr < 2; ++rr) {
                int nl = arow + rr * 64;
                int n = nTile + nl;
                float4 vv = make_float4(0.f, 0.f, 0.f, 0.f);
                if (n < N)
                    vv = *reinterpret_cast<const float4*>(Bm + (size_t)n * K + k0 + acol);
                Bs[acol + 0][nl] = vv.x;
                Bs[acol + 1][nl] = vv.y;
                Bs[acol + 2][nl] = vv.z;
                Bs[acol + 3][nl] = vv.w;
            }
        } else {
#pragma unroll
            for (int rr = 0; rr < 2; ++rr) {
                int kk = (tid >> 5) + rr * 8;
                int nl = (tid & 31) * 4;
                int n = nTile + nl;
                float4 vv = make_float4(0.f, 0.f, 0.f, 0.f);
                if (n < N)
                    vv = *reinterpret_cast<const float4*>(Bm + (size_t)(k0 + kk) * N + n);
                *reinterpret_cast<float4*>(&Bs[kk][nl]) = vv;
            }
        }
        __syncthreads();

#pragma unroll
        for (int k = 0; k < BK; ++k) {
            float4 a0 = *reinterpret_cast<const float4*>(&As[k][ty * 8]);
            float4 a1 = *reinterpret_cast<const float4*>(&As[k][ty * 8 + 4]);
            ulonglong2 b01 = *reinterpret_cast<const ulonglong2*>(&Bs[k][tx * 8]);
            ulonglong2 b23 = *reinterpret_cast<const ulonglong2*>(&Bs[k][tx * 8 + 4]);
            float av[8] = {a0.x, a0.y, a0.z, a0.w, a1.x, a1.y, a1.z, a1.w};
            unsigned long long bv[4] = {b01.x, b01.y, b23.x, b23.y};
#pragma unroll
            for (int i = 0; i < 8; ++i) {
                unsigned long long ad = pack2(av[i], av[i]);
#pragma unroll
                for (int j = 0; j < 4; ++j) fma2(acc[i][j], ad, bv[j]);
            }
        }
        __syncthreads();
    }

    int epi = (flags >> 4) & 3;
#pragma unroll
    for (int i = 0; i < 8; ++i) {
        int m = mTile + ty * 8 + i;
        if (m >= Meff) continue;
        size_t crow = (size_t)m * N;
#pragma unroll
        for (int j = 0; j < 4; ++j) {
            float2 v2 = unpack2(acc[i][j]);
#pragma unroll
            for (int q = 0; q < 2; ++q) {
                int n = nTile + tx * 8 + j * 2 + q;
                if (n >= N) continue;
                float v = (q ? v2.y : v2.x) + (bias ? bias[n] : 0.0f);
                if (epi == 1) {
                    C[crow + n] = fmaxf(v, 0.0f);
                } else if (epi == 2) {
                    float var = expf(v);
                    C[crow + n] = var;
                    int r = g_act[m];
                    C2[crow + n] = 1.0f + sqrtf(var) * eps[(size_t)r * N + n];
                } else {
                    C[crow + n] = v;
                }
            }
        }
    }
}

// ---------------- elementwise kernels ----------------
// outputs for miss rows: w[perm[B/2+j]], var[perm[B/2+j]]
__global__ void gatherout_kernel(float* __restrict__ out_w, float* __restrict__ out_var) {
    int j = blockIdx.y;
    int r = g_perm[BB / 2 + j];
    int p = g_posinact[r];
    int c = (blockIdx.x * 256 + threadIdx.x) * 4;
    float4 wv = *reinterpret_cast<const float4*>(&g_w[(size_t)p * PP + c]);
    float4 vv = *reinterpret_cast<const float4*>(&g_var[(size_t)p * PP + c]);
    *reinterpret_cast<float4*>(&out_w[(size_t)j * PP + c]) = wv;
    *reinterpret_cast<float4*>(&out_var[(size_t)j * PP + c]) = vv;
}

// x_reg = x_rec * softplus(mean + exp(0.5*lreg)*eps_r), scattered to permuted position
__global__ void xreg_kernel(const float* __restrict__ mean, const float* __restrict__ lreg,
                            const float* __restrict__ xrec, const float* __restrict__ eps_r,
                            float* __restrict__ comb) {
    int i = blockIdx.y;
    if (i >= g_na) return;
    int r = g_act[i];
    if (!g_mask[r]) return;
    int d = (blockIdx.x * 256 + threadIdx.x) * 4;
    size_t off = (size_t)i * DD + d;
    float4 mu = *reinterpret_cast<const float4*>(mean + off);
    float4 lg = *reinterpret_cast<const float4*>(lreg + off);
    float4 xr = *reinterpret_cast<const float4*>(xrec + off);
    float4 ep = *reinterpret_cast<const float4*>(eps_r + (size_t)r * DD + d);
    float4 o;
    o.x = xr.x * softplusf(mu.x + expf(0.5f * lg.x) * ep.x);
    o.y = xr.y * softplusf(mu.y + expf(0.5f * lg.y) * ep.y);
    o.z = xr.z * softplusf(mu.z + expf(0.5f * lg.z) * ep.z);
    o.w = xr.w * softplusf(mu.w + expf(0.5f * lg.w) * ep.w);
    *reinterpret_cast<float4*>(comb + (size_t)g_newpos[r] * DD + d) = o;
}

// non-masked rows: combined[j] = x[perm[j]]
__global__ void copy_kernel(const float* __restrict__ x, float* __restrict__ comb) {
    int j = blockIdx.y;
    int r = g_perm[j];
    if (g_mask[r]) return;
    int d = (blockIdx.x * 256 + threadIdx.x) * 4;
    *reinterpret_cast<float4*>(comb + (size_t)j * DD + d) =
        *reinterpret_cast<const float4*>(x + (size_t)r * DD + d);
}

// ---------------- launch ----------------
extern "C" void kernel_launch(void* const* d_in, const int* in_sizes, int n_in,
                              void* d_out, int out_size) {
    const float* x      = (const float*)d_in[0];
    const int*   mm     = (const int*)d_in[1];
    const float* priors = (const float*)d_in[2];
    const float* W1     = (const float*)d_in[3];
    const float* b1     = (const float*)d_in[4];
    const float* W2     = (const float*)d_in[5];
    const float* b2     = (const float*)d_in[6];
    const float* Wr1    = (const float*)d_in[7];
    const float* br1    = (const float*)d_in[8];
    const float* Wlv    = (const float*)d_in[9];
    const float* blv    = (const float*)d_in[10];
    const float* Wg1    = (const float*)d_in[11];
    const float* bg1    = (const float*)d_in[12];
    const float* Wm     = (const float*)d_in[13];
    const float* bm     = (const float*)d_in[14];
    const float* Wl     = (const float*)d_in[15];
    const float* bl     = (const float*)d_in[16];
    const float* eps_w  = (const float*)d_in[17];
    const float* eps_r  = (const float*)d_in[18];
    float* out = (float*)d_out;

    float *ph, *phr, *pxrec, *plreg, *pcomb, *pvar, *pw;
    cudaGetSymbolAddress((void**)&ph, g_h);
    cudaGetSymbolAddress((void**)&phr, g_hr);
    cudaGetSymbolAddress((void**)&pxrec, g_xrec);
    cudaGetSymbolAddress((void**)&plreg, g_lreg);
    cudaGetSymbolAddress((void**)&pcomb, g_comb);
    cudaGetSymbolAddress((void**)&pvar, g_var);
    cudaGetSymbolAddress((void**)&pw, g_w);

    float* out_logits = out;
    float* out_w = out + (size_t)BB * OO;
    float* out_var = out_w + (size_t)(BB - BB / 2) * PP;

    setup_kernel<<<1, 1024>>>(mm);

    dim3 blk(256);
    dim3 gHalfH(HH / BN, BB / BM);   // early-exit handles na < BB
    dim3 gHalfP(PP / BN, BB / BM);
    dim3 gHalfD(DD / BN, BB / BM);

    // h = relu(x[act] @ Wr1^T + br1)
    gemm_kernel<<<gHalfH, blk>>>(x, Wr1, br1, ph, nullptr, nullptr, BB, HH, DD,
                                 1 | 2 | (1 << 4));
    // var = exp(h @ Wlv^T + blv); w = 1 + sqrt(var)*eps_w
    gemm_kernel<<<gHalfP, blk>>>(ph, Wlv, blv, pvar, pw, eps_w, BB, PP, HH,
                                 1 | (2 << 4));
    // write w[miss], var[miss] outputs
    gatherout_kernel<<<dim3(PP / 1024, BB - BB / 2), blk>>>(out_w, out_var);
    // x_rec = w @ priors   (NN: priors is [P, D])
    gemm_kernel<<<gHalfD, blk>>>(pw, priors, nullptr, pxrec, nullptr, nullptr, BB, DD, PP,
                                 1 | 4);
    // hr = relu(x_rec @ Wg1^T + bg1)
    gemm_kernel<<<gHalfH, blk>>>(pxrec, Wg1, bg1, phr, nullptr, nullptr, BB, HH, DD,
                                 1 | (1 << 4));
    // mean_reg = hr @ Wm^T + bm   (reuse g_h)
    gemm_kernel<<<gHalfD, blk>>>(phr, Wm, bm, ph, nullptr, nullptr, BB, DD, HH, 1);
    // lreg = hr @ Wl^T + bl
    gemm_kernel<<<gHalfD, blk>>>(phr, Wl, bl, plreg, nullptr, nullptr, BB, DD, HH, 1);
    // x_reg + scatter into combined
    xreg_kernel<<<dim3(DD / 1024, BB), blk>>>(ph, plreg, pxrec, eps_r, pcomb);
    // copy x rows for non-masked positions
    copy_kernel<<<dim3(DD / 1024, BB), blk>>>(x, pcomb);
    // h1 = relu(combined @ W1^T + b1)   (reuse g_h)
    gemm_kernel<<<dim3(HH / BN, BB / BM), blk>>>(pcomb, W1, b1, ph, nullptr, nullptr,
                                                 BB, HH, DD, (1 << 4));
    // logits = h1 @ W2^T + b2
    gemm_kernel<<<dim3((OO + BN - 1) / BN, BB / BM), blk>>>(ph, W2, b2, out_logits,
                                                            nullptr, nullptr, BB, OO, HH, 0);
}

// round 2
// speedup vs baseline: 1.0015x; 1.0015x over previous
#include <cuda_runtime.h>
#include <cuda_bf16.h>
#include <cstdint>

// Problem constants (fixed shapes)
#define BB 4096
#define DD 4096
#define HH 4096
#define OO 1000
#define PP 2048

// ---------------- scratch (device globals; no allocation) ----------------
__device__ float g_h   [(size_t)BB * HH];   // h / mean_reg / h1 (reused)
__device__ float g_hr  [(size_t)BB * HH];
__device__ float g_xrec[(size_t)BB * DD];
__device__ float g_lreg[(size_t)BB * DD];
__device__ float g_comb[(size_t)BB * DD];
__device__ float g_var [(size_t)BB * PP];
__device__ float g_w   [(size_t)BB * PP];

__device__ int g_na;
__device__ int g_perm[BB];
__device__ int g_newpos[BB];
__device__ int g_act[BB];
__device__ int g_posinact[BB];
__device__ int g_mask[BB];

// ---------------- helpers ----------------
__device__ __forceinline__ unsigned long long pack2(float x, float y) {
    unsigned long long r;
    asm("mov.b64 %0, {%1, %2};" : "=l"(r) : "f"(x), "f"(y));
    return r;
}
__device__ __forceinline__ float2 unpack2(unsigned long long v) {
    float2 r;
    asm("mov.b64 {%0, %1}, %2;" : "=f"(r.x), "=f"(r.y) : "l"(v));
    return r;
}
__device__ __forceinline__ void fma2(unsigned long long& c, unsigned long long a,
                                     unsigned long long b) {
    asm("fma.rn.f32x2 %0, %1, %2, %0;" : "+l"(c) : "l"(a), "l"(b));
}
__device__ __forceinline__ float softplusf(float z) {
    // logaddexp(z, 0) = max(z,0) + log1p(exp(-|z|))
    return fmaxf(z, 0.0f) + log1pf(expf(-fabsf(z)));
}

// ---------------- setup: mask, stable-partition perm, active set ----------------
__global__ void setup_kernel(const int* __restrict__ mm) {
    __shared__ int wsum[32];
    __shared__ int sTot[2];
    int tid = threadIdx.x, lane = tid & 31, warp = tid >> 5;
    int base = tid * 4;

    // ---- scan 1: ones (mask) ----
    int f[4], incl[4];
    int s = 0;
#pragma unroll
    for (int j = 0; j < 4; ++j) {
        f[j] = (mm[base + j] % 2 != 0) ? 1 : 0;
        s += f[j];
        incl[j] = s;
    }
    int v = s;
#pragma unroll
    for (int o = 1; o < 32; o <<= 1) {
        int u = __shfl_up_sync(0xffffffffu, v, o);
        if (lane >= o) v += u;
    }
    if (lane == 31) wsum[warp] = v;
    __syncthreads();
    if (warp == 0) {
        int w = wsum[lane];
#pragma unroll
        for (int o = 1; o < 32; o <<= 1) {
            int u = __shfl_up_sync(0xffffffffu, w, o);
            if (lane >= o) w += u;
        }
        wsum[lane] = w;
        if (lane == 31) sTot[0] = w;
    }
    __syncthreads();
    int T = sTot[0];
    int Z = BB - T;
    int thrExcl = (warp ? wsum[warp - 1] : 0) + (v - s);

    int af[4];
#pragma unroll
    for (int j = 0; j < 4; ++j) {
        int i = base + j;
        int onesBefore = thrExcl + incl[j] - f[j];
        int pos = f[j] ? (Z + onesBefore) : (i - onesBefore);
        g_mask[i] = f[j];
        g_newpos[i] = pos;
        g_perm[pos] = i;
        af[j] = (f[j] || pos >= BB / 2) ? 1 : 0;
    }
    __syncthreads();

    // ---- scan 2: active rows (need VAE path) ----
    int incl2[4];
    int s2 = 0;
#pragma unroll
    for (int j = 0; j < 4; ++j) { s2 += af[j]; incl2[j] = s2; }
    int v2 = s2;
#pragma unroll
    for (int o = 1; o < 32; o <<= 1) {
        int u = __shfl_up_sync(0xffffffffu, v2, o);
        if (lane >= o) v2 += u;
    }
    if (lane == 31) wsum[warp] = v2;
    __syncthreads();
    if (warp == 0) {
        int w = wsum[lane];
#pragma unroll
        for (int o = 1; o < 32; o <<= 1) {
            int u = __shfl_up_sync(0xffffffffu, w, o);
            if (lane >= o) w += u;
        }
        wsum[lane] = w;
        if (lane == 31) sTot[1] = w;
    }
    __syncthreads();
    int thrExcl2 = (warp ? wsum[warp - 1] : 0) + (v2 - s2);
#pragma unroll
    for (int j = 0; j < 4; ++j) {
        int i = base + j;
        int actBefore = thrExcl2 + incl2[j] - af[j];
        if (af[j]) {
            g_act[actBefore] = i;
            g_posinact[i] = actBefore;
        } else {
            g_posinact[i] = -1;
        }
    }
    if (tid == 0) g_na = sTot[1];
}

// ---------------- GEMM: C[M,N] = op(A[M,K]) * B + bias, fused epilogues ----------------
// flags: bit0 = M comes from g_na (early-exit grid)
//        bit1 = gather A rows via g_act
//        bit2 = B is K-major [K,N] ("NN"); else B is [N,K] row-major ("NT", C = A*B^T)
//        bits4+ = epilogue: 0 = +bias, 1 = relu(+bias), 2 = var/w (exp, sqrt, eps_w)
#define BM 128
#define BN 128
#define BK 16

__global__ void __launch_bounds__(256, 2)
gemm_kernel(const float* __restrict__ A, const float* __restrict__ Bm,
            const float* __restrict__ bias, float* __restrict__ C,
            float* __restrict__ C2, const float* __restrict__ eps,
            int M, int N, int K, int flags) {
    int Meff = (flags & 1) ? g_na : M;
    int mTile = blockIdx.y * BM;
    if (mTile >= Meff) return;
    int nTile = blockIdx.x * BN;

    __shared__ float As[BK][BM];
    __shared__ float Bs[BK][BN];

    int tid = threadIdx.x;
    int tx = tid & 15, ty = tid >> 4;
    const bool gather = (flags & 2) != 0;
    const bool bnn = (flags & 4) != 0;

    int arow = tid >> 2;          // 0..63
    int acol = (tid & 3) * 4;     // 0,4,8,12

    unsigned long long acc[8][4] = {};

    for (int k0 = 0; k0 < K; k0 += BK) {
        // load A tile (transposed into As[k][m])
#pragma unroll
        for (int rr = 0; rr < 2; ++rr) {
            int ml = arow + rr * 64;
            int m = mTile + ml;
            float4 vv = make_float4(0.f, 0.f, 0.f, 0.f);
            if (m < Meff) {
                int row = gather ? g_act[m] : m;
                vv = *reinterpret_cast<const float4*>(A + (size_t)row * K + k0 + acol);
            }
            As[acol + 0][ml] = vv.x;
            As[acol + 1][ml] = vv.y;
            As[acol + 2][ml] = vv.z;
            As[acol + 3][ml] = vv.w;
        }
        // load B tile
        if (!bnn) {
#pragma unroll
            for (int rr = 0; rr < 2; ++rr) {
                int nl = arow + rr * 64;
                int n = nTile + nl;
                float4 vv = make_float4(0.f, 0.f, 0.f, 0.f);
                if (n < N)
                    vv = *reinterpret_cast<const float4*>(Bm + (size_t)n * K + k0 + acol);
                Bs[acol + 0][nl] = vv.x;
                Bs[acol + 1][nl] = vv.y;
                Bs[acol + 2][nl] = vv.z;
                Bs[acol + 3][nl] = vv.w;
            }
        } else {
#pragma unroll
            for (int rr = 0; rr < 2; ++rr) {
                int kk = (tid >> 5) + rr * 8;
                int nl = (tid & 31) * 4;
                int n = nTile + nl;
                float4 vv = make_float4(0.f, 0.f, 0.f, 0.f);
                if (n < N)
                    vv = *reinterpret_cast<const float4*>(Bm + (size_t)(k0 + kk) * N + n);
                *reinterpret_cast<float4*>(&Bs[kk][nl]) = vv;
            }
        }
        __syncthreads();

#pragma unroll
        for (int k = 0; k < BK; ++k) {
            float4 a0 = *reinterpret_cast<const float4*>(&As[k][ty * 8]);
            float4 a1 = *reinterpret_cast<const float4*>(&As[k][ty * 8 + 4]);
            ulonglong2 b01 = *reinterpret_cast<const ulonglong2*>(&Bs[k][tx * 8]);
            ulonglong2 b23 = *reinterpret_cast<const ulonglong2*>(&Bs[k][tx * 8 + 4]);
            float av[8] = {a0.x, a0.y, a0.z, a0.w, a1.x, a1.y, a1.z, a1.w};
            unsigned long long bv[4] = {b01.x, b01.y, b23.x, b23.y};
#pragma unroll
            for (int i = 0; i < 8; ++i) {
                unsigned long long ad = pack2(av[i], av[i]);
#pragma unroll
                for (int j = 0; j < 4; ++j) fma2(acc[i][j], ad, bv[j]);
            }
        }
        __syncthreads();
    }

    int epi = (flags >> 4) & 3;
#pragma unroll
    for (int i = 0; i < 8; ++i) {
        int m = mTile + ty * 8 + i;
        if (m >= Meff) continue;
        size_t crow = (size_t)m * N;
#pragma unroll
        for (int j = 0; j < 4; ++j) {
            float2 v2 = unpack2(acc[i][j]);
#pragma unroll
            for (int q = 0; q < 2; ++q) {
                int n = nTile + tx * 8 + j * 2 + q;
                if (n >= N) continue;
                float v = (q ? v2.y : v2.x) + (bias ? bias[n] : 0.0f);
                if (epi == 1) {
                    C[crow + n] = fmaxf(v, 0.0f);
                } else if (epi == 2) {
                    float var = expf(v);
                    C[crow + n] = var;
                    int r = g_act[m];
                    C2[crow + n] = 1.0f + sqrtf(var) * eps[(size_t)r * N + n];
                } else {
                    C[crow + n] = v;
                }
            }
        }
    }
}

// ---------------- elementwise kernels ----------------
// outputs for miss rows: w[perm[B/2+j]], var[perm[B/2+j]]
__global__ void gatherout_kernel(float* __restrict__ out_w, float* __restrict__ out_var) {
    int j = blockIdx.y;
    int r = g_perm[BB / 2 + j];
    int p = g_posinact[r];
    int c = (blockIdx.x * 256 + threadIdx.x) * 4;
    float4 wv = *reinterpret_cast<const float4*>(&g_w[(size_t)p * PP + c]);
    float4 vv = *reinterpret_cast<const float4*>(&g_var[(size_t)p * PP + c]);
    *reinterpret_cast<float4*>(&out_w[(size_t)j * PP + c]) = wv;
    *reinterpret_cast<float4*>(&out_var[(size_t)j * PP + c]) = vv;
}

// x_reg = x_rec * softplus(mean + exp(0.5*lreg)*eps_r), scattered to permuted position
__global__ void xreg_kernel(const float* __restrict__ mean, const float* __restrict__ lreg,
                            const float* __restrict__ xrec, const float* __restrict__ eps_r,
                            float* __restrict__ comb) {
    int i = blockIdx.y;
    if (i >= g_na) return;
    int r = g_act[i];
    if (!g_mask[r]) return;
    int d = (blockIdx.x * 256 + threadIdx.x) * 4;
    size_t off = (size_t)i * DD + d;
    float4 mu = *reinterpret_cast<const float4*>(mean + off);
    float4 lg = *reinterpret_cast<const float4*>(lreg + off);
    float4 xr = *reinterpret_cast<const float4*>(xrec + off);
    float4 ep = *reinterpret_cast<const float4*>(eps_r + (size_t)r * DD + d);
    float4 o;
    o.x = xr.x * softplusf(mu.x + expf(0.5f * lg.x) * ep.x);
    o.y = xr.y * softplusf(mu.y + expf(0.5f * lg.y) * ep.y);
    o.z = xr.z * softplusf(mu.z + expf(0.5f * lg.z) * ep.z);
    o.w = xr.w * softplusf(mu.w + expf(0.5f * lg.w) * ep.w);
    *reinterpret_cast<float4*>(comb + (size_t)g_newpos[r] * DD + d) = o;
}

// non-masked rows: combined[j] = x[perm[j]]
__global__ void copy_kernel(const float* __restrict__ x, float* __restrict__ comb) {
    int j = blockIdx.y;
    int r = g_perm[j];
    if (g_mask[r]) return;
    int d = (blockIdx.x * 256 + threadIdx.x) * 4;
    *reinterpret_cast<float4*>(comb + (size_t)j * DD + d) =
        *reinterpret_cast<const float4*>(x + (size_t)r * DD + d);
}

// ---------------- launch ----------------
extern "C" void kernel_launch(void* const* d_in, const int* in_sizes, int n_in,
                              void* d_out, int out_size) {
    const float* x      = (const float*)d_in[0];
    const int*   mm     = (const int*)d_in[1];
    const float* priors = (const float*)d_in[2];
    const float* W1     = (const float*)d_in[3];
    const float* b1     = (const float*)d_in[4];
    const float* W2     = (const float*)d_in[5];
    const float* b2     = (const float*)d_in[6];
    const float* Wr1    = (const float*)d_in[7];
    const float* br1    = (const float*)d_in[8];
    const float* Wlv    = (const float*)d_in[9];
    const float* blv    = (const float*)d_in[10];
    const float* Wg1    = (const float*)d_in[11];
    const float* bg1    = (const float*)d_in[12];
    const float* Wm     = (const float*)d_in[13];
    const float* bm     = (const float*)d_in[14];
    const float* Wl     = (const float*)d_in[15];
    const float* bl     = (const float*)d_in[16];
    const float* eps_w  = (const float*)d_in[17];
    const float* eps_r  = (const float*)d_in[18];
    float* out = (float*)d_out;

    float *ph, *phr, *pxrec, *plreg, *pcomb, *pvar, *pw;
    cudaGetSymbolAddress((void**)&ph, g_h);
    cudaGetSymbolAddress((void**)&phr, g_hr);
    cudaGetSymbolAddress((void**)&pxrec, g_xrec);
    cudaGetSymbolAddress((void**)&plreg, g_lreg);
    cudaGetSymbolAddress((void**)&pcomb, g_comb);
    cudaGetSymbolAddress((void**)&pvar, g_var);
    cudaGetSymbolAddress((void**)&pw, g_w);

    float* out_logits = out;
    float* out_w = out + (size_t)BB * OO;
    float* out_var = out_w + (size_t)(BB - BB / 2) * PP;

    setup_kernel<<<1, 1024>>>(mm);

    dim3 blk(256);
    dim3 gHalfH(HH / BN, BB / BM);   // early-exit handles na < BB
    dim3 gHalfP(PP / BN, BB / BM);
    dim3 gHalfD(DD / BN, BB / BM);

    // h = relu(x[act] @ Wr1^T + br1)
    gemm_kernel<<<gHalfH, blk>>>(x, Wr1, br1, ph, nullptr, nullptr, BB, HH, DD,
                                 1 | 2 | (1 << 4));
    // var = exp(h @ Wlv^T + blv); w = 1 + sqrt(var)*eps_w
    gemm_kernel<<<gHalfP, blk>>>(ph, Wlv, blv, pvar, pw, eps_w, BB, PP, HH,
                                 1 | (2 << 4));
    // write w[miss], var[miss] outputs
    gatherout_kernel<<<dim3(PP / 1024, BB - BB / 2), blk>>>(out_w, out_var);
    // x_rec = w @ priors   (NN: priors is [P, D])
    gemm_kernel<<<gHalfD, blk>>>(pw, priors, nullptr, pxrec, nullptr, nullptr, BB, DD, PP,
                                 1 | 4);
    // hr = relu(x_rec @ Wg1^T + bg1)
    gemm_kernel<<<gHalfH, blk>>>(pxrec, Wg1, bg1, phr, nullptr, nullptr, BB, HH, DD,
                                 1 | (1 << 4));
    // mean_reg = hr @ Wm^T + bm   (reuse g_h)
    gemm_kernel<<<gHalfD, blk>>>(phr, Wm, bm, ph, nullptr, nullptr, BB, DD, HH, 1);
    // lreg = hr @ Wl^T + bl
    gemm_kernel<<<gHalfD, blk>>>(phr, Wl, bl, plreg, nullptr, nullptr, BB, DD, HH, 1);
    // x_reg + scatter into combined
    xreg_kernel<<<dim3(DD / 1024, BB), blk>>>(ph, plreg, pxrec, eps_r, pcomb);
    // copy x rows for non-masked positions
    copy_kernel<<<dim3(DD / 1024, BB), blk>>>(x, pcomb);
    // h1 = relu(combined @ W1^T + b1)   (reuse g_h)
    gemm_kernel<<<dim3(HH / BN, BB / BM), blk>>>(pcomb, W1, b1, ph, nullptr, nullptr,
                                                 BB, HH, DD, (1 << 4));
    // logits = h1 @ W2^T + b2
    gemm_kernel<<<dim3((OO + BN - 1) / BN, BB / BM), blk>>>(ph, W2, b2, out_logits,
                                                            nullptr, nullptr, BB, OO, HH, 0);
}

// round 4
// speedup vs baseline: 2.5244x; 2.5205x over previous
#include <cuda_runtime.h>
#include <cuda_bf16.h>
#include <cstdint>

#define BB 4096
#define DD 4096
#define HH 4096
#define OO 1000
#define PP 2048

// ---- device scratch ----
__device__ __nv_bfloat16 g_Wr1h[(size_t)HH*DD], g_Wr1l[(size_t)HH*DD];
__device__ __nv_bfloat16 g_Wlvh[(size_t)PP*HH], g_Wlvl[(size_t)PP*HH];
__device__ __nv_bfloat16 g_Wg1h[(size_t)HH*DD], g_Wg1l[(size_t)HH*DD];
__device__ __nv_bfloat16 g_Wmh [(size_t)DD*HH], g_Wml [(size_t)DD*HH];
__device__ __nv_bfloat16 g_Wlh [(size_t)DD*HH], g_Wll [(size_t)DD*HH];
__device__ __nv_bfloat16 g_W1h [(size_t)HH*DD], g_W1l [(size_t)HH*DD];
__device__ __nv_bfloat16 g_W2h [(size_t)OO*HH], g_W2l [(size_t)OO*HH];
__device__ __nv_bfloat16 g_pTh [(size_t)DD*PP], g_pTl [(size_t)DD*PP];
__device__ __nv_bfloat16 g_xah[(size_t)BB*DD], g_xal[(size_t)BB*DD];
__device__ __nv_bfloat16 g_hh [(size_t)BB*HH], g_hl [(size_t)BB*HH];
__device__ __nv_bfloat16 g_wvh[(size_t)BB*PP], g_wvl[(size_t)BB*PP];
__device__ __nv_bfloat16 g_xrh[(size_t)BB*DD], g_xrl[(size_t)BB*DD];
__device__ __nv_bfloat16 g_hrh[(size_t)BB*HH], g_hrl[(size_t)BB*HH];
__device__ __nv_bfloat16 g_cbh[(size_t)BB*DD], g_cbl[(size_t)BB*DD];
__device__ float g_var[(size_t)BB*PP], g_w[(size_t)BB*PP];
__device__ float g_mean[(size_t)BB*DD], g_lreg[(size_t)BB*DD], g_xrecf[(size_t)BB*DD];
__device__ int g_na, g_perm[BB], g_newpos[BB], g_act[BB], g_posinact[BB], g_mask[BB];

// ---- helpers ----
__device__ __forceinline__ float softplusf(float z) {
    return fmaxf(z, 0.0f) + log1pf(expf(-fabsf(z)));
}
__device__ __forceinline__ uint32_t smem_u32(const void* p) {
    uint32_t a;
    asm("{ .reg .u64 t; cvta.to.shared.u64 t, %1; cvt.u32.u64 %0, t; }" : "=r"(a) : "l"(p));
    return a;
}
__device__ __forceinline__ void cpa16(uint32_t dst, const void* src) {
    asm volatile("cp.async.cg.shared.global [%0], [%1], 16;" :: "r"(dst), "l"(src));
}
__device__ __forceinline__ void ldmx4(uint32_t* r, uint32_t a) {
    asm volatile("ldmatrix.sync.aligned.m8n8.x4.shared.b16 {%0,%1,%2,%3}, [%4];"
                 : "=r"(r[0]), "=r"(r[1]), "=r"(r[2]), "=r"(r[3]) : "r"(a));
}
__device__ __forceinline__ void ldmx2(uint32_t* r, uint32_t a) {
    asm volatile("ldmatrix.sync.aligned.m8n8.x2.shared.b16 {%0,%1}, [%2];"
                 : "=r"(r[0]), "=r"(r[1]) : "r"(a));
}
__device__ __forceinline__ void mma16816(float* c, const uint32_t* a, const uint32_t* b) {
    asm volatile("mma.sync.aligned.m16n8k16.row.col.f32.bf16.bf16.f32 "
                 "{%0,%1,%2,%3}, {%4,%5,%6,%7}, {%8,%9}, {%0,%1,%2,%3};"
                 : "+f"(c[0]), "+f"(c[1]), "+f"(c[2]), "+f"(c[3])
                 : "r"(a[0]), "r"(a[1]), "r"(a[2]), "r"(a[3]), "r"(b[0]), "r"(b[1]));
}
__device__ __forceinline__ void split_bf16(float v, __nv_bfloat16& h, __nv_bfloat16& l) {
    h = __float2bfloat16_rn(v);
    l = __float2bfloat16_rn(v - __bfloat162float(h));
}

// ---- setup ----
__global__ void setup_kernel(const int* __restrict__ mm) {
    __shared__ int wsum[32];
    __shared__ int sTot[2];
    int tid = threadIdx.x, lane = tid & 31, warp = tid >> 5;
    int base = tid * 4;
    int f[4], incl[4], s = 0;
#pragma unroll
    for (int j = 0; j < 4; ++j) { f[j] = (mm[base + j] % 2 != 0); s += f[j]; incl[j] = s; }
    int v = s;
#pragma unroll
    for (int o = 1; o < 32; o <<= 1) { int u = __shfl_up_sync(~0u, v, o); if (lane >= o) v += u; }
    if (lane == 31) wsum[warp] = v;
    __syncthreads();
    if (warp == 0) {
        int w = wsum[lane];
#pragma unroll
        for (int o = 1; o < 32; o <<= 1) { int u = __shfl_up_sync(~0u, w, o); if (lane >= o) w += u; }
        wsum[lane] = w;
        if (lane == 31) sTot[0] = w;
    }
    __syncthreads();
    int Z = BB - sTot[0];
    int thrExcl = (warp ? wsum[warp - 1] : 0) + (v - s);
    int af[4];
#pragma unroll
    for (int j = 0; j < 4; ++j) {
        int i = base + j;
        int ones = thrExcl + incl[j] - f[j];
        int pos = f[j] ? (Z + ones) : (i - ones);
        g_mask[i] = f[j]; g_newpos[i] = pos; g_perm[pos] = i;
        af[j] = (f[j] || pos >= BB / 2);
    }
    __syncthreads();
    int incl2[4], s2 = 0;
#pragma unroll
    for (int j = 0; j < 4; ++j) { s2 += af[j]; incl2[j] = s2; }
    int v2 = s2;
#pragma unroll
    for (int o = 1; o < 32; o <<= 1) { int u = __shfl_up_sync(~0u, v2, o); if (lane >= o) v2 += u; }
    if (lane == 31) wsum[warp] = v2;
    __syncthreads();
    if (warp == 0) {
        int w = wsum[lane];
#pragma unroll
        for (int o = 1; o < 32; o <<= 1) { int u = __shfl_up_sync(~0u, w, o); if (lane >= o) w += u; }
        wsum[lane] = w;
        if (lane == 31) sTot[1] = w;
    }
    __syncthreads();
    int thrExcl2 = (warp ? wsum[warp - 1] : 0) + (v2 - s2);
#pragma unroll
    for (int j = 0; j < 4; ++j) {
        int i = base + j;
        int ab = thrExcl2 + incl2[j] - af[j];
        if (af[j]) { g_act[ab] = i; g_posinact[i] = ab; } else g_posinact[i] = -1;
    }
    if (tid == 0) g_na = sTot[1];
}

// ---- conversions ----
__global__ void convw_kernel(const float* __restrict__ W, __nv_bfloat16* __restrict__ hi,
                             __nv_bfloat16* __restrict__ lo) {
    int i = (blockIdx.x * 256 + threadIdx.x) * 4;
    float4 v = *reinterpret_cast<const float4*>(W + i);
    float vv[4] = {v.x, v.y, v.z, v.w};
    __nv_bfloat16 h[4], l[4];
#pragma unroll
    for (int j = 0; j < 4; ++j) split_bf16(vv[j], h[j], l[j]);
    reinterpret_cast<__nv_bfloat162*>(hi + i)[0] = __nv_bfloat162(h[0], h[1]);
    reinterpret_cast<__nv_bfloat162*>(hi + i)[1] = __nv_bfloat162(h[2], h[3]);
    reinterpret_cast<__nv_bfloat162*>(lo + i)[0] = __nv_bfloat162(l[0], l[1]);
    reinterpret_cast<__nv_bfloat162*>(lo + i)[1] = __nv_bfloat162(l[2], l[3]);
}
__global__ void convx_kernel(const float* __restrict__ x) {
    int i = blockIdx.y;
    if (i >= g_na) return;
    int r = g_act[i];
    int d = (blockIdx.x * 256 + threadIdx.x) * 4;
    float4 v = *reinterpret_cast<const float4*>(x + (size_t)r * DD + d);
    float vv[4] = {v.x, v.y, v.z, v.w};
    __nv_bfloat16 h[4], l[4];
#pragma unroll
    for (int j = 0; j < 4; ++j) split_bf16(vv[j], h[j], l[j]);
    size_t o = (size_t)i * DD + d;
    reinterpret_cast<__nv_bfloat162*>(g_xah + o)[0] = __nv_bfloat162(h[0], h[1]);
    reinterpret_cast<__nv_bfloat162*>(g_xah + o)[1] = __nv_bfloat162(h[2], h[3]);
    reinterpret_cast<__nv_bfloat162*>(g_xal + o)[0] = __nv_bfloat162(l[0], l[1]);
    reinterpret_cast<__nv_bfloat162*>(g_xal + o)[1] = __nv_bfloat162(l[2], l[3]);
}
__global__ void convpT_kernel(const float* __restrict__ P) {
    __shared__ float tile[32][33];
    int d0 = blockIdx.x * 32, p0 = blockIdx.y * 32;
    int tx = threadIdx.x, ty = threadIdx.y;
#pragma unroll
    for (int i = 0; i < 4; ++i)
        tile[ty + i * 8][tx] = P[(size_t)(p0 + ty + i * 8) * DD + d0 + tx];
    __syncthreads();
#pragma unroll
    for (int i = 0; i < 4; ++i) {
        __nv_bfloat16 h, l;
        split_bf16(tile[tx][ty + i * 8], h, l);
        size_t o = (size_t)(d0 + ty + i * 8) * PP + p0 + tx;
        g_pTh[o] = h; g_pTl[o] = l;
    }
}

// ---- mma.sync GEMM: C[M,N] = A @ B^T, bf16 hi/lo 3-product ----
// flags: 1=Meff from g_na, 2=relu, 4=f32 out, 8=hi/lo out, 16=var/w epilogue
#define ROWB 80                 // padded row stride (32 bf16 data + 8 pad)
#define TILE_B (128 * ROWB)     // 10240
#define STAGE_B (4 * TILE_B)    // 40960: Ah, Al, Bh, Bl
#define NSTG 4
#define SMEMB (NSTG * STAGE_B + 512)

__global__ void __launch_bounds__(256, 1)
gemm_mma(const __nv_bfloat16* __restrict__ Ah, const __nv_bfloat16* __restrict__ Al,
         const __nv_bfloat16* __restrict__ Bh, const __nv_bfloat16* __restrict__ Bl,
         const float* __restrict__ bias, float* __restrict__ Cf,
         __nv_bfloat16* __restrict__ Ch, __nv_bfloat16* __restrict__ Cl,
         float* __restrict__ Cw, const float* __restrict__ eps,
         int M, int N, int K, int flags)
{
    int Meff = (flags & 1) ? g_na : M;
    int mT = blockIdx.y * 128;
    if (mT >= Meff) return;
    int nT = blockIdx.x * 128;

    extern __shared__ char sm[];
    uint32_t sb = smem_u32(sm);
    float* biasS = reinterpret_cast<float*>(sm + NSTG * STAGE_B);

    int tid = threadIdx.x, wid = tid >> 5, lane = tid & 31;
    int wm = wid & 1, wn = wid >> 1;   // warp tile: rows wm*64.., cols wn*32..

    if (tid < 128) {
        int n = nT + tid;
        biasS[tid] = (bias && n < N) ? bias[n] : 0.0f;
    }

    // stage loader: A/B tiles, hi+lo, 16B chunks
    int chA = tid;                 // thread covers chunks tid, tid+256 of 512
    float acc[4][4][4];
#pragma unroll
    for (int a = 0; a < 4; ++a)
#pragma unroll
        for (int b = 0; b < 4; ++b)
#pragma unroll
            for (int c = 0; c < 4; ++c) acc[a][b][c] = 0.0f;

    int nK = K / 32;

#define LOAD_STAGE(s, k0)                                                        \
    {                                                                            \
        uint32_t st = sb + (s) * STAGE_B;                                        \
        _Pragma("unroll")                                                        \
        for (int i = 0; i < 2; ++i) {                                            \
            int ch = i * 256 + chA;                                              \
            int r = ch >> 2, c16 = ch & 3;                                       \
            int rg = mT + r; rg = rg < Meff ? rg : Meff - 1;                     \
            size_t go = (size_t)rg * K + (k0) + c16 * 8;                         \
            uint32_t off = r * ROWB + c16 * 16;                                  \
            cpa16(st + off, Ah + go);                                            \
            cpa16(st + TILE_B + off, Al + go);                                   \
        }                                                                        \
        _Pragma("unroll")                                                        \
        for (int i = 0; i < 2; ++i) {                                            \
            int ch = i * 256 + chA;                                              \
            int r = ch >> 2, c16 = ch & 3;                                       \
            int rg = nT + r; rg = rg < N ? rg : N - 1;                           \
            size_t go = (size_t)rg * K + (k0) + c16 * 8;                         \
            uint32_t off = r * ROWB + c16 * 16;                                  \
            cpa16(st + 2 * TILE_B + off, Bh + go);                               \
            cpa16(st + 3 * TILE_B + off, Bl + go);                               \
        }                                                                        \
    }

    LOAD_STAGE(0, 0);
    asm volatile("cp.async.commit_group;");
    LOAD_STAGE(1, 32);
    asm volatile("cp.async.commit_group;");
    LOAD_STAGE(2, 64);
    asm volatile("cp.async.commit_group;");

#pragma unroll 1
    for (int it = 0; it < nK; ++it) {
        asm volatile("cp.async.wait_group 2;");
        __syncthreads();
        int ps = it + 3;
        if (ps < nK) LOAD_STAGE(ps & 3, ps * 32);
        asm volatile("cp.async.commit_group;");

        uint32_t st = sb + (it & 3) * STAGE_B;
#pragma unroll
        for (int kh = 0; kh < 2; ++kh) {
            uint32_t ah[4][4], al[4][4], bh[4][2], bl[4][2];
            uint32_t aaddr = st + (wm * 64 + (lane & 15)) * ROWB + kh * 32 +
                             ((lane >> 4) & 1) * 16;
#pragma unroll
            for (int ma = 0; ma < 4; ++ma) {
                ldmx4(ah[ma], aaddr + ma * 16 * ROWB);
                ldmx4(al[ma], aaddr + ma * 16 * ROWB + TILE_B);
            }
            uint32_t baddr = st + 2 * TILE_B + (wn * 32 + (lane & 7)) * ROWB +
                             kh * 32 + ((lane >> 3) & 1) * 16;
#pragma unroll
            for (int na = 0; na < 4; ++na) {
                ldmx2(bh[na], baddr + na * 8 * ROWB);
                ldmx2(bl[na], baddr + na * 8 * ROWB + TILE_B);
            }
#pragma unroll
            for (int ma = 0; ma < 4; ++ma)
#pragma unroll
                for (int na = 0; na < 4; ++na) {
                    mma16816(acc[ma][na], ah[ma], bh[na]);
                    mma16816(acc[ma][na], ah[ma], bl[na]);
                    mma16816(acc[ma][na], al[ma], bh[na]);
                }
        }
    }

    // ---- epilogue ----
    bool relu = flags & 2, f32s = flags & 4, hilos = flags & 8, varw = flags & 16;
#pragma unroll
    for (int ma = 0; ma < 4; ++ma) {
#pragma unroll
        for (int rs = 0; rs < 2; ++rs) {
            int m = mT + wm * 64 + ma * 16 + (lane >> 2) + rs * 8;
            if (m >= Meff) continue;
            size_t ro = (size_t)m * N;
            int ract = varw ? g_act[m] : 0;
#pragma unroll
            for (int na = 0; na < 4; ++na) {
                int nc = wn * 32 + na * 8 + (lane & 3) * 2;
                int n = nT + nc;
                if (n >= N) continue;
                float v0 = acc[ma][na][rs * 2 + 0] + biasS[nc];
                float v1 = acc[ma][na][rs * 2 + 1] + biasS[nc + 1];
                if (relu) { v0 = fmaxf(v0, 0.0f); v1 = fmaxf(v1, 0.0f); }
                if (varw) {
                    float var0 = expf(v0), var1 = expf(v1);
                    Cf[ro + n] = var0; Cf[ro + n + 1] = var1;
                    float w0 = 1.0f + sqrtf(var0) * eps[(size_t)ract * N + n];
                    float w1 = 1.0f + sqrtf(var1) * eps[(size_t)ract * N + n + 1];
                    Cw[ro + n] = w0; Cw[ro + n + 1] = w1;
                    __nv_bfloat16 h0, l0, h1, l1;
                    split_bf16(w0, h0, l0); split_bf16(w1, h1, l1);
                    *reinterpret_cast<__nv_bfloat162*>(Ch + ro + n) = __nv_bfloat162(h0, h1);
                    *reinterpret_cast<__nv_bfloat162*>(Cl + ro + n) = __nv_bfloat162(l0, l1);
                } else {
                    if (f32s) {
                        *reinterpret_cast<float2*>(Cf + ro + n) = make_float2(v0, v1);
                    }
                    if (hilos) {
                        __nv_bfloat16 h0, l0, h1, l1;
                        split_bf16(v0, h0, l0); split_bf16(v1, h1, l1);
                        *reinterpret_cast<__nv_bfloat162*>(Ch + ro + n) = __nv_bfloat162(h0, h1);
                        *reinterpret_cast<__nv_bfloat162*>(Cl + ro + n) = __nv_bfloat162(l0, l1);
                    }
                }
            }
        }
    }
}

// ---- elementwise ----
__global__ void gatherout_kernel(float* __restrict__ out_w, float* __restrict__ out_var) {
    int j = blockIdx.y;
    int r = g_perm[BB / 2 + j];
    int p = g_posinact[r];
    int c = (blockIdx.x * 256 + threadIdx.x) * 4;
    *reinterpret_cast<float4*>(&out_w[(size_t)j * PP + c]) =
        *reinterpret_cast<const float4*>(&g_w[(size_t)p * PP + c]);
    *reinterpret_cast<float4*>(&out_var[(size_t)j * PP + c]) =
        *reinterpret_cast<const float4*>(&g_var[(size_t)p * PP + c]);
}
__global__ void xreg_kernel(const float* __restrict__ eps_r) {
    int i = blockIdx.y;
    if (i >= g_na) return;
    int r = g_act[i];
    if (!g_mask[r]) return;
    int d = (blockIdx.x * 256 + threadIdx.x) * 4;
    size_t off = (size_t)i * DD + d;
    float4 mu = *reinterpret_cast<const float4*>(g_mean + off);
    float4 lg = *reinterpret_cast<const float4*>(g_lreg + off);
    float4 xr = *reinterpret_cast<const float4*>(g_xrecf + off);
    float4 ep = *reinterpret_cast<const float4*>(eps_r + (size_t)r * DD + d);
    float o[4];
    o[0] = xr.x * softplusf(mu.x + expf(0.5f * lg.x) * ep.x);
    o[1] = xr.y * softplusf(mu.y + expf(0.5f * lg.y) * ep.y);
    o[2] = xr.z * softplusf(mu.z + expf(0.5f * lg.z) * ep.z);
    o[3] = xr.w * softplusf(mu.w + expf(0.5f * lg.w) * ep.w);
    __nv_bfloat16 h[4], l[4];
#pragma unroll
    for (int j = 0; j < 4; ++j) split_bf16(o[j], h[j], l[j]);
    size_t dst = (size_t)g_newpos[r] * DD + d;
    reinterpret_cast<__nv_bfloat162*>(g_cbh + dst)[0] = __nv_bfloat162(h[0], h[1]);
    reinterpret_cast<__nv_bfloat162*>(g_cbh + dst)[1] = __nv_bfloat162(h[2], h[3]);
    reinterpret_cast<__nv_bfloat162*>(g_cbl + dst)[0] = __nv_bfloat162(l[0], l[1]);
    reinterpret_cast<__nv_bfloat162*>(g_cbl + dst)[1] = __nv_bfloat162(l[2], l[3]);
}
__global__ void copy_kernel(const float* __restrict__ x) {
    int j = blockIdx.y;
    int r = g_perm[j];
    if (g_mask[r]) return;
    int d = (blockIdx.x * 256 + threadIdx.x) * 4;
    float4 v = *reinterpret_cast<const float4*>(x + (size_t)r * DD + d);
    float vv[4] = {v.x, v.y, v.z, v.w};
    __nv_bfloat16 h[4], l[4];
#pragma unroll
    for (int i = 0; i < 4; ++i) split_bf16(vv[i], h[i], l[i]);
    size_t dst = (size_t)j * DD + d;
    reinterpret_cast<__nv_bfloat162*>(g_cbh + dst)[0] = __nv_bfloat162(h[0], h[1]);
    reinterpret_cast<__nv_bfloat162*>(g_cbh + dst)[1] = __nv_bfloat162(h[2], h[3]);
    reinterpret_cast<__nv_bfloat162*>(g_cbl + dst)[0] = __nv_bfloat162(l[0], l[1]);
    reinterpret_cast<__nv_bfloat162*>(g_cbl + dst)[1] = __nv_bfloat162(l[2], l[3]);
}

// ---- launch ----
static void* sa(const void* s) { void* p = nullptr; cudaGetSymbolAddress(&p, s); return p; }
typedef __nv_bfloat16 bf;

extern "C" void kernel_launch(void* const* d_in, const int* in_sizes, int n_in,
                              void* d_out, int out_size) {
    const float* x      = (const float*)d_in[0];
    const int*   mm     = (const int*)d_in[1];
    const float* priors = (const float*)d_in[2];
    const float* W1  = (const float*)d_in[3];
    const float* b1  = (const float*)d_in[4];
    const float* W2  = (const float*)d_in[5];
    const float* b2  = (const float*)d_in[6];
    const float* Wr1 = (const float*)d_in[7];
    const float* br1 = (const float*)d_in[8];
    const float* Wlv = (const float*)d_in[9];
    const float* blv = (const float*)d_in[10];
    const float* Wg1 = (const float*)d_in[11];
    const float* bg1 = (const float*)d_in[12];
    const float* Wm  = (const float*)d_in[13];
    const float* bm  = (const float*)d_in[14];
    const float* Wl  = (const float*)d_in[15];
    const float* bl  = (const float*)d_in[16];
    const float* eps_w = (const float*)d_in[17];
    const float* eps_r = (const float*)d_in[18];
    float* out = (float*)d_out;
    float* out_logits = out;
    float* out_w = out + (size_t)BB * OO;
    float* out_var = out_w + (size_t)(BB - BB / 2) * PP;

    cudaFuncSetAttribute(gemm_mma, cudaFuncAttributeMaxDynamicSharedMemorySize, SMEMB);

    bf *Wr1h=(bf*)sa(g_Wr1h), *Wr1l=(bf*)sa(g_Wr1l), *Wlvh=(bf*)sa(g_Wlvh), *Wlvl=(bf*)sa(g_Wlvl);
    bf *Wg1h=(bf*)sa(g_Wg1h), *Wg1l=(bf*)sa(g_Wg1l), *Wmh=(bf*)sa(g_Wmh), *Wml=(bf*)sa(g_Wml);
    bf *Wlh=(bf*)sa(g_Wlh), *Wll=(bf*)sa(g_Wll), *W1h=(bf*)sa(g_W1h), *W1l=(bf*)sa(g_W1l);
    bf *W2h=(bf*)sa(g_W2h), *W2l=(bf*)sa(g_W2l), *pTh=(bf*)sa(g_pTh), *pTl=(bf*)sa(g_pTl);
    bf *xah=(bf*)sa(g_xah), *xal=(bf*)sa(g_xal), *hh=(bf*)sa(g_hh), *hl=(bf*)sa(g_hl);
    bf *wvh=(bf*)sa(g_wvh), *wvl=(bf*)sa(g_wvl), *xrh=(bf*)sa(g_xrh), *xrl=(bf*)sa(g_xrl);
    bf *hrh=(bf*)sa(g_hrh), *hrl=(bf*)sa(g_hrl), *cbh=(bf*)sa(g_cbh), *cbl=(bf*)sa(g_cbl);
    float *pvar=(float*)sa(g_var), *pw=(float*)sa(g_w);
    float *pmean=(float*)sa(g_mean), *plreg=(float*)sa(g_lreg), *pxrecf=(float*)sa(g_xrecf);

    setup_kernel<<<1, 1024>>>(mm);
    convw_kernel<<<(HH*DD)/1024, 256>>>(Wr1, Wr1h, Wr1l);
    convw_kernel<<<(PP*HH)/1024, 256>>>(Wlv, Wlvh, Wlvl);
    convw_kernel<<<(HH*DD)/1024, 256>>>(Wg1, Wg1h, Wg1l);
    convw_kernel<<<(DD*HH)/1024, 256>>>(Wm, Wmh, Wml);
    convw_kernel<<<(DD*HH)/1024, 256>>>(Wl, Wlh, Wll);
    convw_kernel<<<(HH*DD)/1024, 256>>>(W1, W1h, W1l);
    convw_kernel<<<(OO*HH)/1024, 256>>>(W2, W2h, W2l);
    convpT_kernel<<<dim3(DD/32, PP/32), dim3(32, 8)>>>(priors);
    convx_kernel<<<dim3(DD/1024, BB), 256>>>(x);

    dim3 blk(256);
    // 1) h = relu(xa @ Wr1^T + br1) -> hi/lo
    gemm_mma<<<dim3(HH/128, BB/128), blk, SMEMB>>>(xah, xal, Wr1h, Wr1l, br1,
        nullptr, hh, hl, nullptr, nullptr, BB, HH, DD, 1|2|8);
    // 2) var = exp(h@Wlv^T+blv); w = 1+sqrt(var)*eps_w -> f32 + hi/lo
    gemm_mma<<<dim3(PP/128, BB/128), blk, SMEMB>>>(hh, hl, Wlvh, Wlvl, blv,
        pvar, wvh, wvl, pw, eps_w, BB, PP, HH, 1|16);
    gatherout_kernel<<<dim3(PP/1024, BB - BB/2), blk>>>(out_w, out_var);
    // 3) x_rec = w @ pT^T -> f32 + hi/lo
    gemm_mma<<<dim3(DD/128, BB/128), blk, SMEMB>>>(wvh, wvl, pTh, pTl, nullptr,
        pxrecf, xrh, xrl, nullptr, nullptr, BB, DD, PP, 1|4|8);
    // 4) hr = relu(x_rec @ Wg1^T + bg1)
    gemm_mma<<<dim3(HH/128, BB/128), blk, SMEMB>>>(xrh, xrl, Wg1h, Wg1l, bg1,
        nullptr, hrh, hrl, nullptr, nullptr, BB, HH, DD, 1|2|8);
    // 5) mean_reg
    gemm_mma<<<dim3(DD/128, BB/128), blk, SMEMB>>>(hrh, hrl, Wmh, Wml, bm,
        pmean, nullptr, nullptr, nullptr, nullptr, BB, DD, HH, 1|4);
    // 6) lreg
    gemm_mma<<<dim3(DD/128, BB/128), blk, SMEMB>>>(hrh, hrl, Wlh, Wll, bl,
        plreg, nullptr, nullptr, nullptr, nullptr, BB, DD, HH, 1|4);
    xreg_kernel<<<dim3(DD/1024, BB), blk>>>(eps_r);
    copy_kernel<<<dim3(DD/1024, BB), blk>>>(x);
    // 7) h1 = relu(comb @ W1^T + b1) (reuse hh/hl)
    gemm_mma<<<dim3(HH/128, BB/128), blk, SMEMB>>>(cbh, cbl, W1h, W1l, b1,
        nullptr, hh, hl, nullptr, nullptr, BB, HH, DD, 2|8);
    // 8) logits
    gemm_mma<<<dim3((OO+127)/128, BB/128), blk, SMEMB>>>(hh, hl, W2h, W2l, b2,
        out_logits, nullptr, nullptr, nullptr, nullptr, BB, OO, HH, 4);
}

// round 5
// speedup vs baseline: 2.7247x; 1.0794x over previous
#include <cuda_runtime.h>
#include <cuda_bf16.h>
#include <cstdint>

#define BB 4096
#define DD 4096
#define HH 4096
#define OO 1000
#define PP 2048

// ---- device scratch ----
__device__ __nv_bfloat16 g_Wr1h[(size_t)HH*DD], g_Wr1l[(size_t)HH*DD];
__device__ __nv_bfloat16 g_Wlvh[(size_t)PP*HH], g_Wlvl[(size_t)PP*HH];
__device__ __nv_bfloat16 g_Wg1h[(size_t)HH*DD], g_Wg1l[(size_t)HH*DD];
__device__ __nv_bfloat16 g_Wch [(size_t)2*DD*HH], g_Wcl [(size_t)2*DD*HH]; // Wm ++ Wl
__device__ __nv_bfloat16 g_W1h [(size_t)HH*DD], g_W1l [(size_t)HH*DD];
__device__ __nv_bfloat16 g_W2h [(size_t)OO*HH], g_W2l [(size_t)OO*HH];
__device__ __nv_bfloat16 g_pTh [(size_t)DD*PP], g_pTl [(size_t)DD*PP];
__device__ __nv_bfloat16 g_xah[(size_t)BB*DD], g_xal[(size_t)BB*DD];
__device__ __nv_bfloat16 g_hh [(size_t)BB*HH], g_hl [(size_t)BB*HH];
__device__ __nv_bfloat16 g_wvh[(size_t)BB*PP], g_wvl[(size_t)BB*PP];
__device__ __nv_bfloat16 g_xrh[(size_t)BB*DD], g_xrl[(size_t)BB*DD];
__device__ __nv_bfloat16 g_hrh[(size_t)BB*HH], g_hrl[(size_t)BB*HH];
__device__ __nv_bfloat16 g_cbh[(size_t)BB*DD], g_cbl[(size_t)BB*DD];
__device__ float g_var[(size_t)BB*PP], g_w[(size_t)BB*PP];
__device__ float g_mean[(size_t)BB*DD], g_lreg[(size_t)BB*DD], g_xrecf[(size_t)BB*DD];
__device__ float g_bcat[2*DD];
__device__ int g_na, g_perm[BB], g_newpos[BB], g_act[BB], g_posinact[BB], g_mask[BB];

// ---- helpers ----
__device__ __forceinline__ float softplusf(float z) {
    return fmaxf(z, 0.0f) + log1pf(expf(-fabsf(z)));
}
__device__ __forceinline__ uint32_t smem_u32(const void* p) {
    uint32_t a;
    asm("{ .reg .u64 t; cvta.to.shared.u64 t, %1; cvt.u32.u64 %0, t; }" : "=r"(a) : "l"(p));
    return a;
}
__device__ __forceinline__ void cpa16(uint32_t dst, const void* src) {
    asm volatile("cp.async.cg.shared.global [%0], [%1], 16;" :: "r"(dst), "l"(src));
}
__device__ __forceinline__ void ldmx4(uint32_t* r, uint32_t a) {
    asm volatile("ldmatrix.sync.aligned.m8n8.x4.shared.b16 {%0,%1,%2,%3}, [%4];"
                 : "=r"(r[0]), "=r"(r[1]), "=r"(r[2]), "=r"(r[3]) : "r"(a));
}
__device__ __forceinline__ void mma16816(float* c, const uint32_t* a, const uint32_t* b) {
    asm volatile("mma.sync.aligned.m16n8k16.row.col.f32.bf16.bf16.f32 "
                 "{%0,%1,%2,%3}, {%4,%5,%6,%7}, {%8,%9}, {%0,%1,%2,%3};"
                 : "+f"(c[0]), "+f"(c[1]), "+f"(c[2]), "+f"(c[3])
                 : "r"(a[0]), "r"(a[1]), "r"(a[2]), "r"(a[3]), "r"(b[0]), "r"(b[1]));
}
__device__ __forceinline__ void split_bf16(float v, __nv_bfloat16& h, __nv_bfloat16& l) {
    h = __float2bfloat16_rn(v);
    l = __float2bfloat16_rn(v - __bfloat162float(h));
}

// ---- setup ----
__global__ void setup_kernel(const int* __restrict__ mm) {
    __shared__ int wsum[32];
    __shared__ int sTot[2];
    int tid = threadIdx.x, lane = tid & 31, warp = tid >> 5;
    int base = tid * 4;
    int f[4], incl[4], s = 0;
#pragma unroll
    for (int j = 0; j < 4; ++j) { f[j] = (mm[base + j] % 2 != 0); s += f[j]; incl[j] = s; }
    int v = s;
#pragma unroll
    for (int o = 1; o < 32; o <<= 1) { int u = __shfl_up_sync(~0u, v, o); if (lane >= o) v += u; }
    if (lane == 31) wsum[warp] = v;
    __syncthreads();
    if (warp == 0) {
        int w = wsum[lane];
#pragma unroll
        for (int o = 1; o < 32; o <<= 1) { int u = __shfl_up_sync(~0u, w, o); if (lane >= o) w += u; }
        wsum[lane] = w;
        if (lane == 31) sTot[0] = w;
    }
    __syncthreads();
    int Z = BB - sTot[0];
    int thrExcl = (warp ? wsum[warp - 1] : 0) + (v - s);
    int af[4];
#pragma unroll
    for (int j = 0; j < 4; ++j) {
        int i = base + j;
        int ones = thrExcl + incl[j] - f[j];
        int pos = f[j] ? (Z + ones) : (i - ones);
        g_mask[i] = f[j]; g_newpos[i] = pos; g_perm[pos] = i;
        af[j] = (f[j] || pos >= BB / 2);
    }
    __syncthreads();
    int incl2[4], s2 = 0;
#pragma unroll
    for (int j = 0; j < 4; ++j) { s2 += af[j]; incl2[j] = s2; }
    int v2 = s2;
#pragma unroll
    for (int o = 1; o < 32; o <<= 1) { int u = __shfl_up_sync(~0u, v2, o); if (lane >= o) v2 += u; }
    if (lane == 31) wsum[warp] = v2;
    __syncthreads();
    if (warp == 0) {
        int w = wsum[lane];
#pragma unroll
        for (int o = 1; o < 32; o <<= 1) { int u = __shfl_up_sync(~0u, w, o); if (lane >= o) w += u; }
        wsum[lane] = w;
        if (lane == 31) sTot[1] = w;
    }
    __syncthreads();
    int thrExcl2 = (warp ? wsum[warp - 1] : 0) + (v2 - s2);
#pragma unroll
    for (int j = 0; j < 4; ++j) {
        int i = base + j;
        int ab = thrExcl2 + incl2[j] - af[j];
        if (af[j]) { g_act[ab] = i; g_posinact[i] = ab; } else g_posinact[i] = -1;
    }
    if (tid == 0) g_na = sTot[1];
}

// ---- conversions ----
__global__ void convw_kernel(const float* __restrict__ W, __nv_bfloat16* __restrict__ hi,
                             __nv_bfloat16* __restrict__ lo) {
    int i = (blockIdx.x * 256 + threadIdx.x) * 4;
    float4 v = *reinterpret_cast<const float4*>(W + i);
    float vv[4] = {v.x, v.y, v.z, v.w};
    __nv_bfloat16 h[4], l[4];
#pragma unroll
    for (int j = 0; j < 4; ++j) split_bf16(vv[j], h[j], l[j]);
    reinterpret_cast<__nv_bfloat162*>(hi + i)[0] = __nv_bfloat162(h[0], h[1]);
    reinterpret_cast<__nv_bfloat162*>(hi + i)[1] = __nv_bfloat162(h[2], h[3]);
    reinterpret_cast<__nv_bfloat162*>(lo + i)[0] = __nv_bfloat162(l[0], l[1]);
    reinterpret_cast<__nv_bfloat162*>(lo + i)[1] = __nv_bfloat162(l[2], l[3]);
}
__global__ void convx_kernel(const float* __restrict__ x) {
    int i = blockIdx.y;
    if (i >= g_na) return;
    int r = g_act[i];
    int d = (blockIdx.x * 256 + threadIdx.x) * 4;
    float4 v = *reinterpret_cast<const float4*>(x + (size_t)r * DD + d);
    float vv[4] = {v.x, v.y, v.z, v.w};
    __nv_bfloat16 h[4], l[4];
#pragma unroll
    for (int j = 0; j < 4; ++j) split_bf16(vv[j], h[j], l[j]);
    size_t o = (size_t)i * DD + d;
    reinterpret_cast<__nv_bfloat162*>(g_xah + o)[0] = __nv_bfloat162(h[0], h[1]);
    reinterpret_cast<__nv_bfloat162*>(g_xah + o)[1] = __nv_bfloat162(h[2], h[3]);
    reinterpret_cast<__nv_bfloat162*>(g_xal + o)[0] = __nv_bfloat162(l[0], l[1]);
    reinterpret_cast<__nv_bfloat162*>(g_xal + o)[1] = __nv_bfloat162(l[2], l[3]);
}
__global__ void convpT_kernel(const float* __restrict__ P) {
    __shared__ float tile[32][33];
    int d0 = blockIdx.x * 32, p0 = blockIdx.y * 32;
    int tx = threadIdx.x, ty = threadIdx.y;
#pragma unroll
    for (int i = 0; i < 4; ++i)
        tile[ty + i * 8][tx] = P[(size_t)(p0 + ty + i * 8) * DD + d0 + tx];
    __syncthreads();
#pragma unroll
    for (int i = 0; i < 4; ++i) {
        __nv_bfloat16 h, l;
        split_bf16(tile[tx][ty + i * 8], h, l);
        size_t o = (size_t)(d0 + ty + i * 8) * PP + p0 + tx;
        g_pTh[o] = h; g_pTl[o] = l;
    }
}
__global__ void concatb_kernel(const float* __restrict__ a, const float* __restrict__ b) {
    int i = blockIdx.x * 256 + threadIdx.x;
    g_bcat[i] = (i < DD) ? a[i] : b[i - DD];
}

// ---- mma.sync GEMM: C[M,N] = A @ B^T, bf16 hi/lo 3-product ----
// flags: 1=Meff from g_na, 2=relu, 4=f32 out, 8=hi/lo out, 16=var/w, 32=dual f32 (mean|lreg)
#define ROWB 80
#define TILE_B (128 * ROWB)
#define STAGE_B (4 * TILE_B)
#define NSTG 4
#define SMEMB (NSTG * STAGE_B + 512)

__global__ void __launch_bounds__(256, 1)
gemm_mma(const __nv_bfloat16* __restrict__ Ah, const __nv_bfloat16* __restrict__ Al,
         const __nv_bfloat16* __restrict__ Bh, const __nv_bfloat16* __restrict__ Bl,
         const float* __restrict__ bias, float* __restrict__ Cf,
         __nv_bfloat16* __restrict__ Ch, __nv_bfloat16* __restrict__ Cl,
         float* __restrict__ Cw, const float* __restrict__ eps,
         int M, int N, int K, int flags)
{
    int Meff = (flags & 1) ? g_na : M;
    int mT = blockIdx.y * 128;
    if (mT >= Meff) return;
    int nT = blockIdx.x * 128;

    extern __shared__ char sm[];
    uint32_t sb = smem_u32(sm);
    float* biasS = reinterpret_cast<float*>(sm + NSTG * STAGE_B);

    int tid = threadIdx.x, wid = tid >> 5, lane = tid & 31;
    int wm = wid & 1, wn = wid >> 1;

    if (tid < 128) {
        int n = nT + tid;
        biasS[tid] = (bias && n < N) ? bias[n] : 0.0f;
    }

    // hoisted fragment base offsets (within a stage buffer)
    uint32_t aBase = (wm * 64 + (lane & 15)) * ROWB + ((lane >> 4) & 1) * 16;
    uint32_t bBase = 2 * TILE_B + (wn * 32 + ((lane >> 4) & 1) * 8 + (lane & 7)) * ROWB +
                     ((lane >> 3) & 1) * 16;

    int chA = tid;
    float acc[4][4][4];
#pragma unroll
    for (int a = 0; a < 4; ++a)
#pragma unroll
        for (int b = 0; b < 4; ++b)
#pragma unroll
            for (int c = 0; c < 4; ++c) acc[a][b][c] = 0.0f;

    int nK = K / 32;

#define LOAD_STAGE(s, k0)                                                        \
    {                                                                            \
        uint32_t st = sb + (s) * STAGE_B;                                        \
        _Pragma("unroll")                                                        \
        for (int i = 0; i < 2; ++i) {                                            \
            int ch = i * 256 + chA;                                              \
            int r = ch >> 2, c16 = ch & 3;                                       \
            int rg = mT + r; rg = rg < Meff ? rg : Meff - 1;                     \
            size_t go = (size_t)rg * K + (k0) + c16 * 8;                         \
            uint32_t off = r * ROWB + c16 * 16;                                  \
            cpa16(st + off, Ah + go);                                            \
            cpa16(st + TILE_B + off, Al + go);                                   \
        }                                                                        \
        _Pragma("unroll")                                                        \
        for (int i = 0; i < 2; ++i) {                                            \
            int ch = i * 256 + chA;                                              \
            int r = ch >> 2, c16 = ch & 3;                                       \
            int rg = nT + r; rg = rg < N ? rg : N - 1;                           \
            size_t go = (size_t)rg * K + (k0) + c16 * 8;                         \
            uint32_t off = r * ROWB + c16 * 16;                                  \
            cpa16(st + 2 * TILE_B + off, Bh + go);                               \
            cpa16(st + 3 * TILE_B + off, Bl + go);                               \
        }                                                                        \
    }

#define LOAD_FRAGS(st, kh, AH, AL, BH, BL)                                       \
    {                                                                            \
        uint32_t ab = (st) + aBase + (kh) * 32;                                  \
        _Pragma("unroll")                                                        \
        for (int ma = 0; ma < 4; ++ma) {                                         \
            ldmx4(AH[ma], ab + ma * 16 * ROWB);                                  \
            ldmx4(AL[ma], ab + ma * 16 * ROWB + TILE_B);                         \
        }                                                                        \
        uint32_t bb = (st) + bBase + (kh) * 32;                                  \
        _Pragma("unroll")                                                        \
        for (int p = 0; p < 2; ++p) {                                            \
            uint32_t t[4];                                                       \
            ldmx4(t, bb + p * 16 * ROWB);                                        \
            BH[2*p][0] = t[0]; BH[2*p][1] = t[1];                                \
            BH[2*p+1][0] = t[2]; BH[2*p+1][1] = t[3];                            \
            ldmx4(t, bb + p * 16 * ROWB + TILE_B);                               \
            BL[2*p][0] = t[0]; BL[2*p][1] = t[1];                                \
            BL[2*p+1][0] = t[2]; BL[2*p+1][1] = t[3];                            \
        }                                                                        \
    }

#define MMA_BLOCK(AH, AL, BH, BL)                                                \
    _Pragma("unroll")                                                            \
    for (int ma = 0; ma < 4; ++ma)                                               \
        _Pragma("unroll")                                                        \
        for (int na = 0; na < 4; ++na) {                                         \
            mma16816(acc[ma][na], AH[ma], BH[na]);                               \
            mma16816(acc[ma][na], AH[ma], BL[na]);                               \
            mma16816(acc[ma][na], AL[ma], BH[na]);                               \
        }

    LOAD_STAGE(0, 0);
    asm volatile("cp.async.commit_group;");
    LOAD_STAGE(1, 32);
    asm volatile("cp.async.commit_group;");
    LOAD_STAGE(2, 64);
    asm volatile("cp.async.commit_group;");

    uint32_t ah[4][4], al[4][4], bh[4][2], bl[4][2];

#pragma unroll 1
    for (int it = 0; it < nK; ++it) {
        asm volatile("cp.async.wait_group 2;");
        __syncthreads();
        uint32_t st = sb + (it & 3) * STAGE_B;
        LOAD_FRAGS(st, 0, ah, al, bh, bl);
        int ps = it + 3;
        if (ps < nK) LOAD_STAGE(ps & 3, ps * 32);
        asm volatile("cp.async.commit_group;");
        MMA_BLOCK(ah, al, bh, bl);
        LOAD_FRAGS(st, 1, ah, al, bh, bl);
        MMA_BLOCK(ah, al, bh, bl);
    }

    // ---- epilogue ----
    bool relu = flags & 2, f32s = flags & 4, hilos = flags & 8;
    bool varw = flags & 16, dual = flags & 32;
#pragma unroll
    for (int ma = 0; ma < 4; ++ma) {
#pragma unroll
        for (int rs = 0; rs < 2; ++rs) {
            int m = mT + wm * 64 + ma * 16 + (lane >> 2) + rs * 8;
            if (m >= Meff) continue;
            size_t ro = (size_t)m * N;
            int ract = varw ? g_act[m] : 0;
#pragma unroll
            for (int na = 0; na < 4; ++na) {
                int nc = wn * 32 + na * 8 + (lane & 3) * 2;
                int n = nT + nc;
                if (n >= N) continue;
                float v0 = acc[ma][na][rs * 2 + 0] + biasS[nc];
                float v1 = acc[ma][na][rs * 2 + 1] + biasS[nc + 1];
                if (relu) { v0 = fmaxf(v0, 0.0f); v1 = fmaxf(v1, 0.0f); }
                if (dual) {
                    size_t rd = (size_t)m * DD;
                    if (n < DD) {
                        *reinterpret_cast<float2*>(Cf + rd + n) = make_float2(v0, v1);
                    } else {
                        *reinterpret_cast<float2*>(Cw + rd + n - DD) = make_float2(v0, v1);
                    }
                } else if (varw) {
                    float var0 = expf(v0), var1 = expf(v1);
                    Cf[ro + n] = var0; Cf[ro + n + 1] = var1;
                    float w0 = 1.0f + sqrtf(var0) * eps[(size_t)ract * N + n];
                    float w1 = 1.0f + sqrtf(var1) * eps[(size_t)ract * N + n + 1];
                    Cw[ro + n] = w0; Cw[ro + n + 1] = w1;
                    __nv_bfloat16 h0, l0, h1, l1;
                    split_bf16(w0, h0, l0); split_bf16(w1, h1, l1);
                    *reinterpret_cast<__nv_bfloat162*>(Ch + ro + n) = __nv_bfloat162(h0, h1);
                    *reinterpret_cast<__nv_bfloat162*>(Cl + ro + n) = __nv_bfloat162(l0, l1);
                } else {
                    if (f32s) {
                        *reinterpret_cast<float2*>(Cf + ro + n) = make_float2(v0, v1);
                    }
                    if (hilos) {
                        __nv_bfloat16 h0, l0, h1, l1;
                        split_bf16(v0, h0, l0); split_bf16(v1, h1, l1);
                        *reinterpret_cast<__nv_bfloat162*>(Ch + ro + n) = __nv_bfloat162(h0, h1);
                        *reinterpret_cast<__nv_bfloat162*>(Cl + ro + n) = __nv_bfloat162(l0, l1);
                    }
                }
            }
        }
    }
}

// ---- elementwise ----
__global__ void gatherout_kernel(float* __restrict__ out_w, float* __restrict__ out_var) {
    int j = blockIdx.y;
    int r = g_perm[BB / 2 + j];
    int p = g_posinact[r];
    int c = (blockIdx.x * 256 + threadIdx.x) * 4;
    *reinterpret_cast<float4*>(&out_w[(size_t)j * PP + c]) =
        *reinterpret_cast<const float4*>(&g_w[(size_t)p * PP + c]);
    *reinterpret_cast<float4*>(&out_var[(size_t)j * PP + c]) =
        *reinterpret_cast<const float4*>(&g_var[(size_t)p * PP + c]);
}
__global__ void xreg_kernel(const float* __restrict__ eps_r) {
    int i = blockIdx.y;
    if (i >= g_na) return;
    int r = g_act[i];
    if (!g_mask[r]) return;
    int d = (blockIdx.x * 256 + threadIdx.x) * 4;
    size_t off = (size_t)i * DD + d;
    float4 mu = *reinterpret_cast<const float4*>(g_mean + off);
    float4 lg = *reinterpret_cast<const float4*>(g_lreg + off);
    float4 xr = *reinterpret_cast<const float4*>(g_xrecf + off);
    float4 ep = *reinterpret_cast<const float4*>(eps_r + (size_t)r * DD + d);
    float o[4];
    o[0] = xr.x * softplusf(mu.x + expf(0.5f * lg.x) * ep.x);
    o[1] = xr.y * softplusf(mu.y + expf(0.5f * lg.y) * ep.y);
    o[2] = xr.z * softplusf(mu.z + expf(0.5f * lg.z) * ep.z);
    o[3] = xr.w * softplusf(mu.w + expf(0.5f * lg.w) * ep.w);
    __nv_bfloat16 h[4], l[4];
#pragma unroll
    for (int j = 0; j < 4; ++j) split_bf16(o[j], h[j], l[j]);
    size_t dst = (size_t)g_newpos[r] * DD + d;
    reinterpret_cast<__nv_bfloat162*>(g_cbh + dst)[0] = __nv_bfloat162(h[0], h[1]);
    reinterpret_cast<__nv_bfloat162*>(g_cbh + dst)[1] = __nv_bfloat162(h[2], h[3]);
    reinterpret_cast<__nv_bfloat162*>(g_cbl + dst)[0] = __nv_bfloat162(l[0], l[1]);
    reinterpret_cast<__nv_bfloat162*>(g_cbl + dst)[1] = __nv_bfloat162(l[2], l[3]);
}
__global__ void copy_kernel(const float* __restrict__ x) {
    int j = blockIdx.y;
    int r = g_perm[j];
    if (g_mask[r]) return;
    int d = (blockIdx.x * 256 + threadIdx.x) * 4;
    float4 v = *reinterpret_cast<const float4*>(x + (size_t)r * DD + d);
    float vv[4] = {v.x, v.y, v.z, v.w};
    __nv_bfloat16 h[4], l[4];
#pragma unroll
    for (int i = 0; i < 4; ++i) split_bf16(vv[i], h[i], l[i]);
    size_t dst = (size_t)j * DD + d;
    reinterpret_cast<__nv_bfloat162*>(g_cbh + dst)[0] = __nv_bfloat162(h[0], h[1]);
    reinterpret_cast<__nv_bfloat162*>(g_cbh + dst)[1] = __nv_bfloat162(h[2], h[3]);
    reinterpret_cast<__nv_bfloat162*>(g_cbl + dst)[0] = __nv_bfloat162(l[0], l[1]);
    reinterpret_cast<__nv_bfloat162*>(g_cbl + dst)[1] = __nv_bfloat162(l[2], l[3]);
}

// ---- launch ----
static void* sa(const void* s) { void* p = nullptr; cudaGetSymbolAddress(&p, s); return p; }
typedef __nv_bfloat16 bf;

extern "C" void kernel_launch(void* const* d_in, const int* in_sizes, int n_in,
                              void* d_out, int out_size) {
    const float* x      = (const float*)d_in[0];
    const int*   mm     = (const int*)d_in[1];
    const float* priors = (const float*)d_in[2];
    const float* W1  = (const float*)d_in[3];
    const float* b1  = (const float*)d_in[4];
    const float* W2  = (const float*)d_in[5];
    const float* b2  = (const float*)d_in[6];
    const float* Wr1 = (const float*)d_in[7];
    const float* br1 = (const float*)d_in[8];
    const float* Wlv = (const float*)d_in[9];
    const float* blv = (const float*)d_in[10];
    const float* Wg1 = (const float*)d_in[11];
    const float* bg1 = (const float*)d_in[12];
    const float* Wm  = (const float*)d_in[13];
    const float* bm  = (const float*)d_in[14];
    const float* Wl  = (const float*)d_in[15];
    const float* bl  = (const float*)d_in[16];
    const float* eps_w = (const float*)d_in[17];
    const float* eps_r = (const float*)d_in[18];
    float* out = (float*)d_out;
    float* out_logits = out;
    float* out_w = out + (size_t)BB * OO;
    float* out_var = out_w + (size_t)(BB - BB / 2) * PP;

    cudaFuncSetAttribute(gemm_mma, cudaFuncAttributeMaxDynamicSharedMemorySize, SMEMB);

    bf *Wr1h=(bf*)sa(g_Wr1h), *Wr1l=(bf*)sa(g_Wr1l), *Wlvh=(bf*)sa(g_Wlvh), *Wlvl=(bf*)sa(g_Wlvl);
    bf *Wg1h=(bf*)sa(g_Wg1h), *Wg1l=(bf*)sa(g_Wg1l);
    bf *Wch=(bf*)sa(g_Wch), *Wcl=(bf*)sa(g_Wcl);
    bf *W1h=(bf*)sa(g_W1h), *W1l=(bf*)sa(g_W1l);
    bf *W2h=(bf*)sa(g_W2h), *W2l=(bf*)sa(g_W2l), *pTh=(bf*)sa(g_pTh), *pTl=(bf*)sa(g_pTl);
    bf *xah=(bf*)sa(g_xah), *xal=(bf*)sa(g_xal), *hh=(bf*)sa(g_hh), *hl=(bf*)sa(g_hl);
    bf *wvh=(bf*)sa(g_wvh), *wvl=(bf*)sa(g_wvl), *xrh=(bf*)sa(g_xrh), *xrl=(bf*)sa(g_xrl);
    bf *hrh=(bf*)sa(g_hrh), *hrl=(bf*)sa(g_hrl), *cbh=(bf*)sa(g_cbh), *cbl=(bf*)sa(g_cbl);
    float *pvar=(float*)sa(g_var), *pw=(float*)sa(g_w);
    float *pmean=(float*)sa(g_mean), *plreg=(float*)sa(g_lreg), *pxrecf=(float*)sa(g_xrecf);
    float *pbcat=(float*)sa(g_bcat);

    setup_kernel<<<1, 1024>>>(mm);
    convw_kernel<<<(HH*DD)/1024, 256>>>(Wr1, Wr1h, Wr1l);
    convw_kernel<<<(PP*HH)/1024, 256>>>(Wlv, Wlvh, Wlvl);
    convw_kernel<<<(HH*DD)/1024, 256>>>(Wg1, Wg1h, Wg1l);
    convw_kernel<<<(DD*HH)/1024, 256>>>(Wm, Wch, Wcl);
    convw_kernel<<<(DD*HH)/1024, 256>>>(Wl, Wch + (size_t)DD*HH, Wcl + (size_t)DD*HH);
    convw_kernel<<<(HH*DD)/1024, 256>>>(W1, W1h, W1l);
    convw_kernel<<<(OO*HH)/1024, 256>>>(W2, W2h, W2l);
    convpT_kernel<<<dim3(DD/32, PP/32), dim3(32, 8)>>>(priors);
    convx_kernel<<<dim3(DD/1024, BB), 256>>>(x);
    concatb_kernel<<<(2*DD)/256, 256>>>(bm, bl);

    dim3 blk(256);
    // 1) h = relu(xa @ Wr1^T + br1) -> hi/lo
    gemm_mma<<<dim3(HH/128, BB/128), blk, SMEMB>>>(xah, xal, Wr1h, Wr1l, br1,
        nullptr, hh, hl, nullptr, nullptr, BB, HH, DD, 1|2|8);
    // 2) var = exp(h@Wlv^T+blv); w = 1+sqrt(var)*eps_w
    gemm_mma<<<dim3(PP/128, BB/128), blk, SMEMB>>>(hh, hl, Wlvh, Wlvl, blv,
        pvar, wvh, wvl, pw, eps_w, BB, PP, HH, 1|16);
    gatherout_kernel<<<dim3(PP/1024, BB - BB/2), blk>>>(out_w, out_var);
    // 3) x_rec = w @ pT^T -> f32 + hi/lo
    gemm_mma<<<dim3(DD/128, BB/128), blk, SMEMB>>>(wvh, wvl, pTh, pTl, nullptr,
        pxrecf, xrh, xrl, nullptr, nullptr, BB, DD, PP, 1|4|8);
    // 4) hr = relu(x_rec @ Wg1^T + bg1)
    gemm_mma<<<dim3(HH/128, BB/128), blk, SMEMB>>>(xrh, xrl, Wg1h, Wg1l, bg1,
        nullptr, hrh, hrl, nullptr, nullptr, BB, HH, DD, 1|2|8);
    // 5+6 fused) [mean | lreg] = hr @ [Wm;Wl]^T + [bm;bl]
    gemm_mma<<<dim3((2*DD)/128, BB/128), blk, SMEMB>>>(hrh, hrl, Wch, Wcl, pbcat,
        pmean, nullptr, nullptr, plreg, nullptr, BB, 2*DD, HH, 1|32);
    xreg_kernel<<<dim3(DD/1024, BB), blk>>>(eps_r);
    copy_kernel<<<dim3(DD/1024, BB), blk>>>(x);
    // 7) h1 = relu(comb @ W1^T + b1) (reuse hh/hl)
    gemm_mma<<<dim3(HH/128, BB/128), blk, SMEMB>>>(cbh, cbl, W1h, W1l, b1,
        nullptr, hh, hl, nullptr, nullptr, BB, HH, DD, 2|8);
    // 8) logits
    gemm_mma<<<dim3((OO+127)/128, BB/128), blk, SMEMB>>>(hh, hl, W2h, W2l, b2,
        out_logits, nullptr, nullptr, nullptr, nullptr, BB, OO, HH, 4);
}

// round 6
// speedup vs baseline: 3.0212x; 1.1088x over previous
#include <cuda_runtime.h>
#include <cuda_bf16.h>
#include <cstdint>

#define BB 4096
#define DD 4096
#define HH 4096
#define OO 1000
#define PP 2048

// ---- device scratch ----
__device__ __nv_bfloat16 g_Wr1h[(size_t)HH*DD], g_Wr1l[(size_t)HH*DD];
__device__ __nv_bfloat16 g_Wlvh[(size_t)PP*HH], g_Wlvl[(size_t)PP*HH];
__device__ __nv_bfloat16 g_Wg1h[(size_t)HH*DD], g_Wg1l[(size_t)HH*DD];
__device__ __nv_bfloat16 g_Wch [(size_t)2*DD*HH], g_Wcl [(size_t)2*DD*HH]; // Wm ++ Wl
__device__ __nv_bfloat16 g_W1h [(size_t)HH*DD], g_W1l [(size_t)HH*DD];
__device__ __nv_bfloat16 g_W2h [(size_t)OO*HH], g_W2l [(size_t)OO*HH];
__device__ __nv_bfloat16 g_pTh [(size_t)DD*PP], g_pTl [(size_t)DD*PP];
__device__ __nv_bfloat16 g_xah[(size_t)BB*DD], g_xal[(size_t)BB*DD];
__device__ __nv_bfloat16 g_hh [(size_t)BB*HH], g_hl [(size_t)BB*HH];
__device__ __nv_bfloat16 g_wvh[(size_t)BB*PP], g_wvl[(size_t)BB*PP];
__device__ __nv_bfloat16 g_xrh[(size_t)BB*DD], g_xrl[(size_t)BB*DD];
__device__ __nv_bfloat16 g_hrh[(size_t)BB*HH], g_hrl[(size_t)BB*HH];
__device__ __nv_bfloat16 g_cbh[(size_t)BB*DD], g_cbl[(size_t)BB*DD];
__device__ float g_var[(size_t)BB*PP], g_w[(size_t)BB*PP];
__device__ float g_mean[(size_t)BB*DD], g_lreg[(size_t)BB*DD], g_xrecf[(size_t)BB*DD];
__device__ float g_bcat[2*DD];
__device__ int g_na, g_perm[BB], g_newpos[BB], g_act[BB], g_posinact[BB], g_mask[BB];

// ---- helpers ----
__device__ __forceinline__ float softplusf(float z) {
    return fmaxf(z, 0.0f) + log1pf(expf(-fabsf(z)));
}
__device__ __forceinline__ uint32_t smem_u32(const void* p) {
    uint32_t a;
    asm("{ .reg .u64 t; cvta.to.shared.u64 t, %1; cvt.u32.u64 %0, t; }" : "=r"(a) : "l"(p));
    return a;
}
__device__ __forceinline__ void cpa16(uint32_t dst, const void* src) {
    asm volatile("cp.async.cg.shared.global [%0], [%1], 16;" :: "r"(dst), "l"(src));
}
__device__ __forceinline__ void ldmx4(uint32_t* r, uint32_t a) {
    asm volatile("ldmatrix.sync.aligned.m8n8.x4.shared.b16 {%0,%1,%2,%3}, [%4];"
                 : "=r"(r[0]), "=r"(r[1]), "=r"(r[2]), "=r"(r[3]) : "r"(a));
}
__device__ __forceinline__ void mma16816(float* c, const uint32_t* a, const uint32_t* b) {
    asm("mma.sync.aligned.m16n8k16.row.col.f32.bf16.bf16.f32 "
        "{%0,%1,%2,%3}, {%4,%5,%6,%7}, {%8,%9}, {%0,%1,%2,%3};"
        : "+f"(c[0]), "+f"(c[1]), "+f"(c[2]), "+f"(c[3])
        : "r"(a[0]), "r"(a[1]), "r"(a[2]), "r"(a[3]), "r"(b[0]), "r"(b[1]));
}
__device__ __forceinline__ void split_bf16(float v, __nv_bfloat16& h, __nv_bfloat16& l) {
    h = __float2bfloat16_rn(v);
    l = __float2bfloat16_rn(v - __bfloat162float(h));
}

// ---- setup ----
__global__ void setup_kernel(const int* __restrict__ mm) {
    __shared__ int wsum[32];
    __shared__ int sTot[2];
    int tid = threadIdx.x, lane = tid & 31, warp = tid >> 5;
    int base = tid * 4;
    int f[4], incl[4], s = 0;
#pragma unroll
    for (int j = 0; j < 4; ++j) { f[j] = (mm[base + j] % 2 != 0); s += f[j]; incl[j] = s; }
    int v = s;
#pragma unroll
    for (int o = 1; o < 32; o <<= 1) { int u = __shfl_up_sync(~0u, v, o); if (lane >= o) v += u; }
    if (lane == 31) wsum[warp] = v;
    __syncthreads();
    if (warp == 0) {
        int w = wsum[lane];
#pragma unroll
        for (int o = 1; o < 32; o <<= 1) { int u = __shfl_up_sync(~0u, w, o); if (lane >= o) w += u; }
        wsum[lane] = w;
        if (lane == 31) sTot[0] = w;
    }
    __syncthreads();
    int Z = BB - sTot[0];
    int thrExcl = (warp ? wsum[warp - 1] : 0) + (v - s);
    int af[4];
#pragma unroll
    for (int j = 0; j < 4; ++j) {
        int i = base + j;
        int ones = thrExcl + incl[j] - f[j];
        int pos = f[j] ? (Z + ones) : (i - ones);
        g_mask[i] = f[j]; g_newpos[i] = pos; g_perm[pos] = i;
        af[j] = (f[j] || pos >= BB / 2);
    }
    __syncthreads();
    int incl2[4], s2 = 0;
#pragma unroll
    for (int j = 0; j < 4; ++j) { s2 += af[j]; incl2[j] = s2; }
    int v2 = s2;
#pragma unroll
    for (int o = 1; o < 32; o <<= 1) { int u = __shfl_up_sync(~0u, v2, o); if (lane >= o) v2 += u; }
    if (lane == 31) wsum[warp] = v2;
    __syncthreads();
    if (warp == 0) {
        int w = wsum[lane];
#pragma unroll
        for (int o = 1; o < 32; o <<= 1) { int u = __shfl_up_sync(~0u, w, o); if (lane >= o) w += u; }
        wsum[lane] = w;
        if (lane == 31) sTot[1] = w;
    }
    __syncthreads();
    int thrExcl2 = (warp ? wsum[warp - 1] : 0) + (v2 - s2);
#pragma unroll
    for (int j = 0; j < 4; ++j) {
        int i = base + j;
        int ab = thrExcl2 + incl2[j] - af[j];
        if (af[j]) { g_act[ab] = i; g_posinact[i] = ab; } else g_posinact[i] = -1;
    }
    if (tid == 0) g_na = sTot[1];
}

// ---- conversions ----
__global__ void convw_kernel(const float* __restrict__ W, __nv_bfloat16* __restrict__ hi,
                             __nv_bfloat16* __restrict__ lo) {
    int i = (blockIdx.x * 256 + threadIdx.x) * 4;
    float4 v = *reinterpret_cast<const float4*>(W + i);
    float vv[4] = {v.x, v.y, v.z, v.w};
    __nv_bfloat16 h[4], l[4];
#pragma unroll
    for (int j = 0; j < 4; ++j) split_bf16(vv[j], h[j], l[j]);
    reinterpret_cast<__nv_bfloat162*>(hi + i)[0] = __nv_bfloat162(h[0], h[1]);
    reinterpret_cast<__nv_bfloat162*>(hi + i)[1] = __nv_bfloat162(h[2], h[3]);
    reinterpret_cast<__nv_bfloat162*>(lo + i)[0] = __nv_bfloat162(l[0], l[1]);
    reinterpret_cast<__nv_bfloat162*>(lo + i)[1] = __nv_bfloat162(l[2], l[3]);
}
__global__ void convx_kernel(const float* __restrict__ x) {
    int i = blockIdx.y;
    if (i >= g_na) return;
    int r = g_act[i];
    int d = (blockIdx.x * 256 + threadIdx.x) * 4;
    float4 v = *reinterpret_cast<const float4*>(x + (size_t)r * DD + d);
    float vv[4] = {v.x, v.y, v.z, v.w};
    __nv_bfloat16 h[4], l[4];
#pragma unroll
    for (int j = 0; j < 4; ++j) split_bf16(vv[j], h[j], l[j]);
    size_t o = (size_t)i * DD + d;
    reinterpret_cast<__nv_bfloat162*>(g_xah + o)[0] = __nv_bfloat162(h[0], h[1]);
    reinterpret_cast<__nv_bfloat162*>(g_xah + o)[1] = __nv_bfloat162(h[2], h[3]);
    reinterpret_cast<__nv_bfloat162*>(g_xal + o)[0] = __nv_bfloat162(l[0], l[1]);
    reinterpret_cast<__nv_bfloat162*>(g_xal + o)[1] = __nv_bfloat162(l[2], l[3]);
}
__global__ void convpT_kernel(const float* __restrict__ P) {
    __shared__ float tile[32][33];
    int d0 = blockIdx.x * 32, p0 = blockIdx.y * 32;
    int tx = threadIdx.x, ty = threadIdx.y;
#pragma unroll
    for (int i = 0; i < 4; ++i)
        tile[ty + i * 8][tx] = P[(size_t)(p0 + ty + i * 8) * DD + d0 + tx];
    __syncthreads();
#pragma unroll
    for (int i = 0; i < 4; ++i) {
        __nv_bfloat16 h, l;
        split_bf16(tile[tx][ty + i * 8], h, l);
        size_t o = (size_t)(d0 + ty + i * 8) * PP + p0 + tx;
        g_pTh[o] = h; g_pTl[o] = l;
    }
}
__global__ void concatb_kernel(const float* __restrict__ a, const float* __restrict__ b) {
    int i = blockIdx.x * 256 + threadIdx.x;
    g_bcat[i] = (i < DD) ? a[i] : b[i - DD];
}

// ---- mma.sync GEMM: C[M,N] = A @ B^T, bf16 hi/lo 3-product, 512 threads ----
// flags: 1=Meff from g_na, 2=relu, 4=f32 out, 8=hi/lo out, 16=var/w, 32=dual f32 (mean|lreg)
#define ROWB 80
#define TILE_B (128 * ROWB)
#define STAGE_B (4 * TILE_B)
#define NSTG 4
#define SMEMB (NSTG * STAGE_B + 512)

__global__ void __launch_bounds__(512, 1)
gemm_mma(const __nv_bfloat16* __restrict__ Ah, const __nv_bfloat16* __restrict__ Al,
         const __nv_bfloat16* __restrict__ Bh, const __nv_bfloat16* __restrict__ Bl,
         const float* __restrict__ bias, float* __restrict__ Cf,
         __nv_bfloat16* __restrict__ Ch, __nv_bfloat16* __restrict__ Cl,
         float* __restrict__ Cw, const float* __restrict__ eps,
         int M, int N, int K, int flags)
{
    int Meff = (flags & 1) ? g_na : M;
    int mT = blockIdx.y * 128;
    if (mT >= Meff) return;
    int nT = blockIdx.x * 128;

    extern __shared__ char sm[];
    uint32_t sb = smem_u32(sm);
    float* biasS = reinterpret_cast<float*>(sm + NSTG * STAGE_B);

    int tid = threadIdx.x, wid = tid >> 5, lane = tid & 31;
    int wm = wid & 3, wn = wid >> 2;   // warp tile: 32 rows (wm), 32 cols (wn)

    if (tid < 128) {
        int n = nT + tid;
        biasS[tid] = (bias && n < N) ? bias[n] : 0.0f;
    }

    // hoisted fragment base offsets (within a stage buffer)
    uint32_t aBase = (wm * 32 + (lane & 15)) * ROWB + ((lane >> 4) & 1) * 16;
    uint32_t bBase = 2 * TILE_B + (wn * 32 + ((lane >> 4) & 1) * 8 + (lane & 7)) * ROWB +
                     ((lane >> 3) & 1) * 16;

    float acc[2][4][4];
#pragma unroll
    for (int a = 0; a < 2; ++a)
#pragma unroll
        for (int b = 0; b < 4; ++b)
#pragma unroll
            for (int c = 0; c < 4; ++c) acc[a][b][c] = 0.0f;

    int nK = K / 32;

#define LOAD_STAGE(s, k0)                                                        \
    {                                                                            \
        uint32_t st = sb + (s) * STAGE_B;                                        \
        {                                                                        \
            int r = tid >> 2, c16 = tid & 3;                                     \
            int rg = mT + r; rg = rg < Meff ? rg : Meff - 1;                     \
            size_t go = (size_t)rg * K + (k0) + c16 * 8;                         \
            uint32_t off = r * ROWB + c16 * 16;                                  \
            cpa16(st + off, Ah + go);                                            \
            cpa16(st + TILE_B + off, Al + go);                                   \
        }                                                                        \
        {                                                                        \
            int r = tid >> 2, c16 = tid & 3;                                     \
            int rg = nT + r; rg = rg < N ? rg : N - 1;                           \
            size_t go = (size_t)rg * K + (k0) + c16 * 8;                         \
            uint32_t off = r * ROWB + c16 * 16;                                  \
            cpa16(st + 2 * TILE_B + off, Bh + go);                               \
            cpa16(st + 3 * TILE_B + off, Bl + go);                               \
        }                                                                        \
    }

#define LOAD_FRAGS(st, kh, AH, AL, BH, BL)                                       \
    {                                                                            \
        uint32_t ab = (st) + aBase + (kh) * 32;                                  \
        _Pragma("unroll")                                                        \
        for (int ma = 0; ma < 2; ++ma) {                                         \
            ldmx4(AH[ma], ab + ma * 16 * ROWB);                                  \
            ldmx4(AL[ma], ab + ma * 16 * ROWB + TILE_B);                         \
        }                                                                        \
        uint32_t bb = (st) + bBase + (kh) * 32;                                  \
        _Pragma("unroll")                                                        \
        for (int p = 0; p < 2; ++p) {                                            \
            uint32_t t[4];                                                       \
            ldmx4(t, bb + p * 16 * ROWB);                                        \
            BH[2*p][0] = t[0]; BH[2*p][1] = t[1];                                \
            BH[2*p+1][0] = t[2]; BH[2*p+1][1] = t[3];                            \
            ldmx4(t, bb + p * 16 * ROWB + TILE_B);                               \
            BL[2*p][0] = t[0]; BL[2*p][1] = t[1];                                \
            BL[2*p+1][0] = t[2]; BL[2*p+1][1] = t[3];                            \
        }                                                                        \
    }

// product-major order: 8 independent MMAs between accumulator reuse
#define MMA_BLOCK(AH, AL, BH, BL)                                                \
    {                                                                            \
        _Pragma("unroll")                                                        \
        for (int ma = 0; ma < 2; ++ma)                                           \
            _Pragma("unroll")                                                    \
            for (int na = 0; na < 4; ++na) mma16816(acc[ma][na], AH[ma], BH[na]);\
        _Pragma("unroll")                                                        \
        for (int ma = 0; ma < 2; ++ma)                                           \
            _Pragma("unroll")                                                    \
            for (int na = 0; na < 4; ++na) mma16816(acc[ma][na], AH[ma], BL[na]);\
        _Pragma("unroll")                                                        \
        for (int ma = 0; ma < 2; ++ma)                                           \
            _Pragma("unroll")                                                    \
            for (int na = 0; na < 4; ++na) mma16816(acc[ma][na], AL[ma], BH[na]);\
    }

    LOAD_STAGE(0, 0);
    asm volatile("cp.async.commit_group;");
    LOAD_STAGE(1, 32);
    asm volatile("cp.async.commit_group;");
    LOAD_STAGE(2, 64);
    asm volatile("cp.async.commit_group;");

    uint32_t ah[2][4], al[2][4], bh[4][2], bl[4][2];

#pragma unroll 1
    for (int it = 0; it < nK; ++it) {
        asm volatile("cp.async.wait_group 2;");
        __syncthreads();
        uint32_t st = sb + (it & 3) * STAGE_B;
        LOAD_FRAGS(st, 0, ah, al, bh, bl);
        int ps = it + 3;
        if (ps < nK) LOAD_STAGE(ps & 3, ps * 32);
        asm volatile("cp.async.commit_group;");
        MMA_BLOCK(ah, al, bh, bl);
        LOAD_FRAGS(st, 1, ah, al, bh, bl);
        MMA_BLOCK(ah, al, bh, bl);
    }

    // ---- epilogue ----
    bool relu = flags & 2, f32s = flags & 4, hilos = flags & 8;
    bool varw = flags & 16, dual = flags & 32;
#pragma unroll
    for (int ma = 0; ma < 2; ++ma) {
#pragma unroll
        for (int rs = 0; rs < 2; ++rs) {
            int m = mT + wm * 32 + ma * 16 + (lane >> 2) + rs * 8;
            if (m >= Meff) continue;
            size_t ro = (size_t)m * N;
            int ract = varw ? g_act[m] : 0;
#pragma unroll
            for (int na = 0; na < 4; ++na) {
                int nc = wn * 32 + na * 8 + (lane & 3) * 2;
                int n = nT + nc;
                if (n >= N) continue;
                float v0 = acc[ma][na][rs * 2 + 0] + biasS[nc];
                float v1 = acc[ma][na][rs * 2 + 1] + biasS[nc + 1];
                if (relu) { v0 = fmaxf(v0, 0.0f); v1 = fmaxf(v1, 0.0f); }
                if (dual) {
                    size_t rd = (size_t)m * DD;
                    if (n < DD) {
                        *reinterpret_cast<float2*>(Cf + rd + n) = make_float2(v0, v1);
                    } else {
                        *reinterpret_cast<float2*>(Cw + rd + n - DD) = make_float2(v0, v1);
                    }
                } else if (varw) {
                    float var0 = expf(v0), var1 = expf(v1);
                    Cf[ro + n] = var0; Cf[ro + n + 1] = var1;
                    float w0 = 1.0f + sqrtf(var0) * eps[(size_t)ract * N + n];
                    float w1 = 1.0f + sqrtf(var1) * eps[(size_t)ract * N + n + 1];
                    Cw[ro + n] = w0; Cw[ro + n + 1] = w1;
                    __nv_bfloat16 h0, l0, h1, l1;
                    split_bf16(w0, h0, l0); split_bf16(w1, h1, l1);
                    *reinterpret_cast<__nv_bfloat162*>(Ch + ro + n) = __nv_bfloat162(h0, h1);
                    *reinterpret_cast<__nv_bfloat162*>(Cl + ro + n) = __nv_bfloat162(l0, l1);
                } else {
                    if (f32s) {
                        *reinterpret_cast<float2*>(Cf + ro + n) = make_float2(v0, v1);
                    }
                    if (hilos) {
                        __nv_bfloat16 h0, l0, h1, l1;
                        split_bf16(v0, h0, l0); split_bf16(v1, h1, l1);
                        *reinterpret_cast<__nv_bfloat162*>(Ch + ro + n) = __nv_bfloat162(h0, h1);
                        *reinterpret_cast<__nv_bfloat162*>(Cl + ro + n) = __nv_bfloat162(l0, l1);
                    }
                }
            }
        }
    }
}

// ---- elementwise ----
__global__ void gatherout_kernel(float* __restrict__ out_w, float* __restrict__ out_var) {
    int j = blockIdx.y;
    int r = g_perm[BB / 2 + j];
    int p = g_posinact[r];
    int c = (blockIdx.x * 256 + threadIdx.x) * 4;
    *reinterpret_cast<float4*>(&out_w[(size_t)j * PP + c]) =
        *reinterpret_cast<const float4*>(&g_w[(size_t)p * PP + c]);
    *reinterpret_cast<float4*>(&out_var[(size_t)j * PP + c]) =
        *reinterpret_cast<const float4*>(&g_var[(size_t)p * PP + c]);
}
__global__ void xreg_kernel(const float* __restrict__ eps_r) {
    int i = blockIdx.y;
    if (i >= g_na) return;
    int r = g_act[i];
    if (!g_mask[r]) return;
    int d = (blockIdx.x * 256 + threadIdx.x) * 4;
    size_t off = (size_t)i * DD + d;
    float4 mu = *reinterpret_cast<const float4*>(g_mean + off);
    float4 lg = *reinterpret_cast<const float4*>(g_lreg + off);
    float4 xr = *reinterpret_cast<const float4*>(g_xrecf + off);
    float4 ep = *reinterpret_cast<const float4*>(eps_r + (size_t)r * DD + d);
    float o[4];
    o[0] = xr.x * softplusf(mu.x + expf(0.5f * lg.x) * ep.x);
    o[1] = xr.y * softplusf(mu.y + expf(0.5f * lg.y) * ep.y);
    o[2] = xr.z * softplusf(mu.z + expf(0.5f * lg.z) * ep.z);
    o[3] = xr.w * softplusf(mu.w + expf(0.5f * lg.w) * ep.w);
    __nv_bfloat16 h[4], l[4];
#pragma unroll
    for (int j = 0; j < 4; ++j) split_bf16(o[j], h[j], l[j]);
    size_t dst = (size_t)g_newpos[r] * DD + d;
    reinterpret_cast<__nv_bfloat162*>(g_cbh + dst)[0] = __nv_bfloat162(h[0], h[1]);
    reinterpret_cast<__nv_bfloat162*>(g_cbh + dst)[1] = __nv_bfloat162(h[2], h[3]);
    reinterpret_cast<__nv_bfloat162*>(g_cbl + dst)[0] = __nv_bfloat162(l[0], l[1]);
    reinterpret_cast<__nv_bfloat162*>(g_cbl + dst)[1] = __nv_bfloat162(l[2], l[3]);
}
__global__ void copy_kernel(const float* __restrict__ x) {
    int j = blockIdx.y;
    int r = g_perm[j];
    if (g_mask[r]) return;
    int d = (blockIdx.x * 256 + threadIdx.x) * 4;
    float4 v = *reinterpret_cast<const float4*>(x + (size_t)r * DD + d);
    float vv[4] = {v.x, v.y, v.z, v.w};
    __nv_bfloat16 h[4], l[4];
#pragma unroll
    for (int i = 0; i < 4; ++i) split_bf16(vv[i], h[i], l[i]);
    size_t dst = (size_t)j * DD + d;
    reinterpret_cast<__nv_bfloat162*>(g_cbh + dst)[0] = __nv_bfloat162(h[0], h[1]);
    reinterpret_cast<__nv_bfloat162*>(g_cbh + dst)[1] = __nv_bfloat162(h[2], h[3]);
    reinterpret_cast<__nv_bfloat162*>(g_cbl + dst)[0] = __nv_bfloat162(l[0], l[1]);
    reinterpret_cast<__nv_bfloat162*>(g_cbl + dst)[1] = __nv_bfloat162(l[2], l[3]);
}

// ---- launch ----
static void* sa(const void* s) { void* p = nullptr; cudaGetSymbolAddress(&p, s); return p; }
typedef __nv_bfloat16 bf;

extern "C" void kernel_launch(void* const* d_in, const int* in_sizes, int n_in,
                              void* d_out, int out_size) {
    const float* x      = (const float*)d_in[0];
    const int*   mm     = (const int*)d_in[1];
    const float* priors = (const float*)d_in[2];
    const float* W1  = (const float*)d_in[3];
    const float* b1  = (const float*)d_in[4];
    const float* W2  = (const float*)d_in[5];
    const float* b2  = (const float*)d_in[6];
    const float* Wr1 = (const float*)d_in[7];
    const float* br1 = (const float*)d_in[8];
    const float* Wlv = (const float*)d_in[9];
    const float* blv = (const float*)d_in[10];
    const float* Wg1 = (const float*)d_in[11];
    const float* bg1 = (const float*)d_in[12];
    const float* Wm  = (const float*)d_in[13];
    const float* bm  = (const float*)d_in[14];
    const float* Wl  = (const float*)d_in[15];
    const float* bl  = (const float*)d_in[16];
    const float* eps_w = (const float*)d_in[17];
    const float* eps_r = (const float*)d_in[18];
    float* out = (float*)d_out;
    float* out_logits = out;
    float* out_w = out + (size_t)BB * OO;
    float* out_var = out_w + (size_t)(BB - BB / 2) * PP;

    cudaFuncSetAttribute(gemm_mma, cudaFuncAttributeMaxDynamicSharedMemorySize, SMEMB);

    bf *Wr1h=(bf*)sa(g_Wr1h), *Wr1l=(bf*)sa(g_Wr1l), *Wlvh=(bf*)sa(g_Wlvh), *Wlvl=(bf*)sa(g_Wlvl);
    bf *Wg1h=(bf*)sa(g_Wg1h), *Wg1l=(bf*)sa(g_Wg1l);
    bf *Wch=(bf*)sa(g_Wch), *Wcl=(bf*)sa(g_Wcl);
    bf *W1h=(bf*)sa(g_W1h), *W1l=(bf*)sa(g_W1l);
    bf *W2h=(bf*)sa(g_W2h), *W2l=(bf*)sa(g_W2l), *pTh=(bf*)sa(g_pTh), *pTl=(bf*)sa(g_pTl);
    bf *xah=(bf*)sa(g_xah), *xal=(bf*)sa(g_xal), *hh=(bf*)sa(g_hh), *hl=(bf*)sa(g_hl);
    bf *wvh=(bf*)sa(g_wvh), *wvl=(bf*)sa(g_wvl), *xrh=(bf*)sa(g_xrh), *xrl=(bf*)sa(g_xrl);
    bf *hrh=(bf*)sa(g_hrh), *hrl=(bf*)sa(g_hrl), *cbh=(bf*)sa(g_cbh), *cbl=(bf*)sa(g_cbl);
    float *pvar=(float*)sa(g_var), *pw=(float*)sa(g_w);
    float *pmean=(float*)sa(g_mean), *plreg=(float*)sa(g_lreg), *pxrecf=(float*)sa(g_xrecf);
    float *pbcat=(float*)sa(g_bcat);

    setup_kernel<<<1, 1024>>>(mm);
    convw_kernel<<<(HH*DD)/1024, 256>>>(Wr1, Wr1h, Wr1l);
    convw_kernel<<<(PP*HH)/1024, 256>>>(Wlv, Wlvh, Wlvl);
    convw_kernel<<<(HH*DD)/1024, 256>>>(Wg1, Wg1h, Wg1l);
    convw_kernel<<<(DD*HH)/1024, 256>>>(Wm, Wch, Wcl);
    convw_kernel<<<(DD*HH)/1024, 256>>>(Wl, Wch + (size_t)DD*HH, Wcl + (size_t)DD*HH);
    convw_kernel<<<(HH*DD)/1024, 256>>>(W1, W1h, W1l);
    convw_kernel<<<(OO*HH)/1024, 256>>>(W2, W2h, W2l);
    convpT_kernel<<<dim3(DD/32, PP/32), dim3(32, 8)>>>(priors);
    convx_kernel<<<dim3(DD/1024, BB), 256>>>(x);
    concatb_kernel<<<(2*DD)/256, 256>>>(bm, bl);

    dim3 blk(512);
    // 1) h = relu(xa @ Wr1^T + br1) -> hi/lo
    gemm_mma<<<dim3(HH/128, BB/128), blk, SMEMB>>>(xah, xal, Wr1h, Wr1l, br1,
        nullptr, hh, hl, nullptr, nullptr, BB, HH, DD, 1|2|8);
    // 2) var = exp(h@Wlv^T+blv); w = 1+sqrt(var)*eps_w
    gemm_mma<<<dim3(PP/128, BB/128), blk, SMEMB>>>(hh, hl, Wlvh, Wlvl, blv,
        pvar, wvh, wvl, pw, eps_w, BB, PP, HH, 1|16);
    gatherout_kernel<<<dim3(PP/1024, BB - BB/2), 256>>>(out_w, out_var);
    // 3) x_rec = w @ pT^T -> f32 + hi/lo
    gemm_mma<<<dim3(DD/128, BB/128), blk, SMEMB>>>(wvh, wvl, pTh, pTl, nullptr,
        pxrecf, xrh, xrl, nullptr, nullptr, BB, DD, PP, 1|4|8);
    // 4) hr = relu(x_rec @ Wg1^T + bg1)
    gemm_mma<<<dim3(HH/128, BB/128), blk, SMEMB>>>(xrh, xrl, Wg1h, Wg1l, bg1,
        nullptr, hrh, hrl, nullptr, nullptr, BB, HH, DD, 1|2|8);
    // 5+6 fused) [mean | lreg] = hr @ [Wm;Wl]^T + [bm;bl]
    gemm_mma<<<dim3((2*DD)/128, BB/128), blk, SMEMB>>>(hrh, hrl, Wch, Wcl, pbcat,
        pmean, nullptr, nullptr, plreg, nullptr, BB, 2*DD, HH, 1|32);
    xreg_kernel<<<dim3(DD/1024, BB), 256>>>(eps_r);
    copy_kernel<<<dim3(DD/1024, BB), 256>>>(x);
    // 7) h1 = relu(comb @ W1^T + b1) (reuse hh/hl)
    gemm_mma<<<dim3(HH/128, BB/128), blk, SMEMB>>>(cbh, cbl, W1h, W1l, b1,
        nullptr, hh, hl, nullptr, nullptr, BB, HH, DD, 2|8);
    // 8) logits
    gemm_mma<<<dim3((OO+127)/128, BB/128), blk, SMEMB>>>(hh, hl, W2h, W2l, b2,
        out_logits, nullptr, nullptr, nullptr, nullptr, BB, OO, HH, 4);
}